// round 15
// baseline (speedup 1.0000x reference)
#include <cuda_runtime.h>
#include <cuda_fp16.h>
#include <math.h>
#include <stdint.h>

// ---------------------------------------------------------------------------
// Problem constants
// ---------------------------------------------------------------------------
#define B_  16
#define C_  512
#define N_  1024
#define HW  32
#define SPITCH 12                      // smem row stride in u32 (48B) - conflict-free
#define NSTG 4                         // pipeline stages
#define ASTG (256 * SPITCH * 4)        // 12288 B per A stage (256 rows)
#define BSTG (128 * SPITCH * 4)        // 6144 B per B stage (128 rows)
#define SMEM_DYN (NSTG * (ASTG + BSTG))   // 73728 B

static constexpr size_t TSZ  = (size_t)B_ * C_ * N_;
static constexpr size_t SSZ  = (size_t)B_ * N_ * N_;
static constexpr size_t VPT  = (size_t)16 * 256 * 1024;   // V halfs per (j,point)
static constexpr size_t MPT  = (size_t)16 * 256 * 512;    // M floats per (j,point)

// ---------------------------------------------------------------------------
// Scratch (static device globals; no allocation anywhere)
// ---------------------------------------------------------------------------
__device__ float g_S [6 * SSZ];
__device__ float g_ex[TSZ], g_q [TSZ], g_q1[TSZ];
__device__ float g_u [3 * TSZ];
__device__ float g_M32[(size_t)3 * 16 * MPT];      // winograd GEMM results

__device__ __align__(128) __half g_P16[6 * SSZ];
__device__ __align__(128) __half g_OT [6 * TSZ];   // attention outputs [p][c]
__device__ __align__(128) __half g_aT [3 * TSZ];   // fusion outputs [p][c]
__device__ __align__(128) __half g_rhT[3 * TSZ];
__device__ __align__(128) __half g_V  [(size_t)3 * 16 * VPT];   // winograd data
__device__ __align__(128) __half g_Uf [(size_t)16 * C_ * (2 * C_)]; // transformed wf
__device__ __align__(128) __half g_Uo [(size_t)16 * C_ * (2 * C_)]; // transformed wo
__device__ __align__(128) __half g_ex16a [TSZ], g_q16a [TSZ], g_q116a[TSZ];
__device__ __align__(128) __half g_ex16b [TSZ], g_q16b [TSZ], g_q116b[TSZ];
__device__ __align__(128) __half g_exT16a[TSZ], g_qT16a[TSZ], g_q1T16a[TSZ];
__device__ __align__(128) __half g_exT16b[TSZ], g_qT16b[TSZ], g_q1T16b[TSZ];
__device__ __align__(128) __half g_in1T16[TSZ], g_in2T16[TSZ], g_in3T16[TSZ];
__device__ __align__(128) __half g_wru16[(size_t)(2 * C_) * (2 * C_)];
__device__ __align__(128) __half g_wc16 [(size_t)C_ * (2 * C_)];

// ---------------------------------------------------------------------------
// Helpers
// ---------------------------------------------------------------------------
__device__ __forceinline__ const __half* sel3(int i, const __half* a,
                                              const __half* b, const __half* c) {
    return i == 0 ? a : (i == 1 ? b : c);
}
__device__ __forceinline__ __half* sel3h(int i, __half* a, __half* b, __half* c) {
    return i == 0 ? a : (i == 1 ? b : c);
}
__device__ __forceinline__ float* sel3f(int i, float* a, float* b, float* c) {
    return i == 0 ? a : (i == 1 ? b : c);
}
__device__ __forceinline__ const float* sel3cf(int i, const float* a,
                                               const float* b, const float* c) {
    return i == 0 ? a : (i == 1 ? b : c);
}
__device__ __forceinline__ int pairB(int j) {
    switch (j) { case 0: return 1; case 1: return 2; case 2: return 0;
                 case 3: return 2; case 4: return 0; default: return 1; }
}
__device__ __forceinline__ float sigm(float x) { return 1.f / (1.f + __expf(-x)); }

__device__ __forceinline__ void cpa16(uint32_t dst, const void* src, uint32_t sz) {
    asm volatile("cp.async.ca.shared.global [%0], [%1], 16, %2;"
                 :: "r"(dst), "l"(src), "r"(sz) : "memory");
}
#define CP_COMMIT() asm volatile("cp.async.commit_group;" ::: "memory")
#define CP_WAIT2()  asm volatile("cp.async.wait_group 2;" ::: "memory")

// ---------------------------------------------------------------------------
// fp16 mma.sync microkernel. Block tile 256x128, 8 warps (4m x 2n of 64x64).
// ---------------------------------------------------------------------------
__device__ __forceinline__ void mma16(float* d, const uint32_t* a, uint32_t b0, uint32_t b1) {
    asm volatile(
        "mma.sync.aligned.m16n8k16.row.col.f32.f16.f16.f32 "
        "{%0,%1,%2,%3}, {%4,%5,%6,%7}, {%8,%9}, {%0,%1,%2,%3};\n"
        : "+f"(d[0]), "+f"(d[1]), "+f"(d[2]), "+f"(d[3])
        : "r"(a[0]), "r"(a[1]), "r"(a[2]), "r"(a[3]), "r"(b0), "r"(b1));
}

__device__ __forceinline__ void ldsm4(uint32_t* r, uint32_t addr) {
    asm volatile(
        "ldmatrix.sync.aligned.m8n8.x4.shared.b16 {%0,%1,%2,%3}, [%4];"
        : "=r"(r[0]), "=r"(r[1]), "=r"(r[2]), "=r"(r[3]) : "r"(addr));
}

__device__ __forceinline__ void compute16(uint32_t aB, uint32_t bB,
                                          float (*acc)[8][4], int wm, int wn,
                                          int lane) {
    int lr = lane & 15;
    uint32_t lc = (uint32_t)(lane >> 4) * 16;
    uint32_t a[4][4], b[4][4];
#pragma unroll
    for (int mt = 0; mt < 4; ++mt)
        ldsm4(a[mt], aB + (uint32_t)(wm + mt * 16 + lr) * (SPITCH * 4) + lc);
#pragma unroll
    for (int np = 0; np < 4; ++np)
        ldsm4(b[np], bB + (uint32_t)(wn + np * 16 + lr) * (SPITCH * 4) + lc);
#pragma unroll
    for (int mt = 0; mt < 4; ++mt)
#pragma unroll
        for (int np = 0; np < 4; ++np) {
            mma16(acc[mt][2 * np],     a[mt], b[np][0], b[np][2]);
            mma16(acc[mt][2 * np + 1], a[mt], b[np][1], b[np][3]);
        }
}

#define ZERO_ACC(acc)                                       \
    float acc[4][8][4];                                     \
    _Pragma("unroll")                                       \
    for (int i_ = 0; i_ < 4; ++i_)                          \
        _Pragma("unroll")                                   \
        for (int j_ = 0; j_ < 8; ++j_)                      \
            _Pragma("unroll")                               \
            for (int v_ = 0; v_ < 4; ++v_) acc[i_][j_][v_] = 0.f;

#define GEMM_PRE()                                                           \
    extern __shared__ __align__(1024) char dsm[];                            \
    int t = threadIdx.x, lane = t & 31, wid = t >> 5;                        \
    int wm = (wid & 3) * 64, wn = (wid >> 2) * 64;                           \
    int g = lane >> 2, tg = lane & 3;                                        \
    uint32_t sAs = (uint32_t)__cvta_generic_to_shared(dsm);                  \
    uint32_t sBs = sAs + NSTG * ASTG;                                        \
    (void)g; (void)tg;

#define GEMM_PIPE(KI, ISSUE, acc)                                            \
    for (int s_ = 0; s_ < 3; ++s_) { ISSUE(s_); CP_COMMIT(); }               \
    for (int it_ = 0; it_ < (KI); ++it_) {                                   \
        CP_WAIT2();                                                          \
        __syncthreads();                                                     \
        compute16(sAs + (it_ & 3) * ASTG, sBs + (it_ & 3) * BSTG,            \
                  acc, wm, wn, lane);                                        \
        if (it_ + 3 < (KI)) ISSUE(it_ + 3);                                  \
        CP_COMMIT();                                                         \
    }

// ---------------------------------------------------------------------------
// k_scores_all: 6 logits GEMMs, 256x128 tiles. grid (8,4,96), 256 thr
// ---------------------------------------------------------------------------
__global__ void __launch_bounds__(256, 1) k_scores_all(
        const __half* __restrict__ exT, const __half* __restrict__ qT,
        const __half* __restrict__ q1T, float* __restrict__ S) {
    GEMM_PRE();
    int z = blockIdx.z, j = z >> 4, b = z & 15;
    const __half* A  = sel3(j >> 1,   exT, qT, q1T);
    const __half* Bm = sel3(pairB(j), exT, qT, q1T);
    int n0 = blockIdx.y * 256, m0 = blockIdx.x * 128;
    const __half* arow = A  + (size_t)b * N_ * C_ + (size_t)(n0 + t) * C_;
    const __half* brow = Bm + (size_t)b * N_ * C_ + (size_t)(m0 + (t & 127)) * C_;
    float* Sb = S + (size_t)j * SSZ + (size_t)b * N_ * N_;

    auto issue = [&](int it) {
        uint32_t da = sAs + (it & 3) * ASTG + t * 48;
        const __half* pa = arow + it * 16;
        cpa16(da, pa, 16); cpa16(da + 16, pa + 8, 16);
        if (t < 128) {
            uint32_t db = sBs + (it & 3) * BSTG + t * 48;
            const __half* pb = brow + it * 16;
            cpa16(db, pb, 16); cpa16(db + 16, pb + 8, 16);
        }
    };

    ZERO_ACC(acc);
    GEMM_PIPE(C_ / 16, issue, acc);

#pragma unroll
    for (int mt = 0; mt < 4; ++mt)
#pragma unroll
        for (int nt = 0; nt < 8; ++nt) {
            int row = n0 + wm + mt * 16 + g;
            int col = m0 + wn + nt * 8 + tg * 2;
            *(float2*)(Sb + (size_t)row * N_ + col)       = make_float2(acc[mt][nt][0], acc[mt][nt][1]);
            *(float2*)(Sb + (size_t)(row + 8) * N_ + col) = make_float2(acc[mt][nt][2], acc[mt][nt][3]);
        }
}

// ---------------------------------------------------------------------------
// Row softmax over all 6 matrices. grid 6*B_*N_, 256 thr
// ---------------------------------------------------------------------------
__global__ void __launch_bounds__(256) k_softmax_all(const float* __restrict__ S,
                                                     __half* __restrict__ P) {
    const float* row = S + (size_t)blockIdx.x * N_;
    __half*      out = P + (size_t)blockIdx.x * N_;
    int t = threadIdx.x;
    float4 v = *(const float4*)(row + 4 * t);
    __shared__ float red[8];

    float m = fmaxf(fmaxf(v.x, v.y), fmaxf(v.z, v.w));
#pragma unroll
    for (int o = 16; o; o >>= 1) m = fmaxf(m, __shfl_xor_sync(0xffffffffu, m, o));
    if ((t & 31) == 0) red[t >> 5] = m;
    __syncthreads();
    float mx = red[0];
#pragma unroll
    for (int i = 1; i < 8; ++i) mx = fmaxf(mx, red[i]);
    __syncthreads();

    v.x = __expf(v.x - mx); v.y = __expf(v.y - mx);
    v.z = __expf(v.z - mx); v.w = __expf(v.w - mx);
    float s = v.x + v.y + v.z + v.w;
#pragma unroll
    for (int o = 16; o; o >>= 1) s += __shfl_xor_sync(0xffffffffu, s, o);
    if ((t & 31) == 0) red[t >> 5] = s;
    __syncthreads();
    float tot = red[0];
#pragma unroll
    for (int i = 1; i < 8; ++i) tot += red[i];
    float inv = 1.f / tot;

    *(__half2*)(out + 4 * t)     = __floats2half2_rn(v.x * inv, v.y * inv);
    *(__half2*)(out + 4 * t + 2) = __floats2half2_rn(v.z * inv, v.w * inv);
}

// ---------------------------------------------------------------------------
// k_attmmT_all: 6 attention-output GEMMs, fp16 [p][c], 256x128 tiles.
// ---------------------------------------------------------------------------
__global__ void __launch_bounds__(256, 1) k_attmmT_all(
        const __half* __restrict__ P,
        const __half* __restrict__ ex16, const __half* __restrict__ q16,
        const __half* __restrict__ q116, __half* __restrict__ OT) {
    GEMM_PRE();
    int z = blockIdx.z, j = z >> 4, b = z & 15;
    const __half* Bn = sel3(pairB(j), ex16, q16, q116);
    int n0 = blockIdx.y * 256, c0 = blockIdx.x * 128;
    const __half* arow = P  + (size_t)j * SSZ + (size_t)b * N_ * N_ + (size_t)(n0 + t) * N_;
    const __half* brow = Bn + (size_t)b * C_ * N_ + (size_t)(c0 + (t & 127)) * N_;
    __half* Ob = OT + (size_t)j * TSZ + (size_t)b * N_ * C_;

    auto issue = [&](int it) {
        uint32_t da = sAs + (it & 3) * ASTG + t * 48;
        const __half* pa = arow + it * 16;
        cpa16(da, pa, 16); cpa16(da + 16, pa + 8, 16);
        if (t < 128) {
            uint32_t db = sBs + (it & 3) * BSTG + t * 48;
            const __half* pb = brow + it * 16;
            cpa16(db, pb, 16); cpa16(db + 16, pb + 8, 16);
        }
    };

    ZERO_ACC(acc);
    GEMM_PIPE(N_ / 16, issue, acc);

#pragma unroll
    for (int mt = 0; mt < 4; ++mt)
#pragma unroll
        for (int nt = 0; nt < 8; ++nt) {
            int row = n0 + wm + mt * 16 + g;
            int col = c0 + wn + nt * 8 + tg * 2;
            *(__half2*)(Ob + (size_t)row * C_ + col) =
                __floats2half2_rn(acc[mt][nt][0], acc[mt][nt][1]);
            *(__half2*)(Ob + (size_t)(row + 8) * C_ + col) =
                __floats2half2_rn(acc[mt][nt][2], acc[mt][nt][3]);
        }
}

// ---------------------------------------------------------------------------
// Winograd data transform core: two [p][c] fp16 sources -> V.
// ---------------------------------------------------------------------------
__device__ __forceinline__ void dtrans_core(const __half2* x0, const __half2* x1,
                                            __half2* V2, size_t base,
                                            int tile, int b, int t) {
    int ty = tile >> 4, tx = tile & 15;
#pragma unroll
    for (int cc = 0; cc < 2; ++cc) {
        const __half2* src = cc ? x1 : x0;
        int ci2 = t + 256 * cc;
        float lo[4][4], hi[4][4];
#pragma unroll
        for (int r = 0; r < 4; ++r) {
            int iy = 2 * ty - 1 + r;
#pragma unroll
            for (int s = 0; s < 4; ++s) {
                int ix = 2 * tx - 1 + s;
                float2 v = make_float2(0.f, 0.f);
                if ((unsigned)iy < HW && (unsigned)ix < HW)
                    v = __half22float2(src[(size_t)(iy * HW + ix) * 256 + t]);
                lo[r][s] = v.x; hi[r][s] = v.y;
            }
        }
        float tl[4][4], th[4][4];
#pragma unroll
        for (int s = 0; s < 4; ++s) {
            tl[0][s] = lo[0][s] - lo[2][s];  th[0][s] = hi[0][s] - hi[2][s];
            tl[1][s] = lo[1][s] + lo[2][s];  th[1][s] = hi[1][s] + hi[2][s];
            tl[2][s] = lo[2][s] - lo[1][s];  th[2][s] = hi[2][s] - hi[1][s];
            tl[3][s] = lo[1][s] - lo[3][s];  th[3][s] = hi[1][s] - hi[3][s];
        }
#pragma unroll
        for (int r = 0; r < 4; ++r) {
            float vl[4], vh[4];
            vl[0] = tl[r][0] - tl[r][2];  vh[0] = th[r][0] - th[r][2];
            vl[1] = tl[r][1] + tl[r][2];  vh[1] = th[r][1] + th[r][2];
            vl[2] = tl[r][2] - tl[r][1];  vh[2] = th[r][2] - th[r][1];
            vl[3] = tl[r][1] - tl[r][3];  vh[3] = th[r][1] - th[r][3];
#pragma unroll
            for (int c = 0; c < 4; ++c) {
                int p = r * 4 + c;
                V2[base + (size_t)p * (VPT / 2)
                   + ((size_t)b * 256 + tile) * 512 + ci2] = __floats2half2_rn(vl[c], vh[c]);
            }
        }
    }
}

// Fusion-conv data transform: sources = OT pair. grid (256, 48=j*16+b)
__global__ void k_dtransF(const __half* __restrict__ OT, __half* __restrict__ V) {
    int tile = blockIdx.x;
    int zb = blockIdx.y, j = zb >> 4, b = zb & 15;
    const __half2* x0 = (const __half2*)(OT + (size_t)(2 * j)     * TSZ + (size_t)b * N_ * C_);
    const __half2* x1 = (const __half2*)(OT + (size_t)(2 * j + 1) * TSZ + (size_t)b * N_ * C_);
    dtrans_core(x0, x1, (__half2*)V, ((size_t)j * 16) * (VPT / 2), tile, b, threadIdx.x);
}

// Final-conv data transform: sources = [stateT ; inT]. grid (256, 48=s*16+b)
__global__ void k_dtransO(const __half* __restrict__ exT, const __half* __restrict__ qT,
                          const __half* __restrict__ q1T,
                          const __half* __restrict__ i1T, const __half* __restrict__ i2T,
                          const __half* __restrict__ i3T, __half* __restrict__ V) {
    int tile = blockIdx.x;
    int zb = blockIdx.y, s = zb >> 4, b = zb & 15;
    const __half2* x0 = (const __half2*)(sel3(s, exT, qT, q1T)   + (size_t)b * N_ * C_);
    const __half2* x1 = (const __half2*)(sel3(s, i1T, i2T, i3T) + (size_t)b * N_ * C_);
    dtrans_core(x0, x1, (__half2*)V, ((size_t)s * 16) * (VPT / 2), tile, b, threadIdx.x);
}

// ---------------------------------------------------------------------------
// Winograd weight transform: U_p[co][ci] from original fp32 weights [co][ci][3][3]
// grid 2048, 256 thr
// ---------------------------------------------------------------------------
__global__ void k_wt_wino(const float* __restrict__ w, __half* __restrict__ U) {
    size_t i = (size_t)blockIdx.x * 256 + threadIdx.x;
    int ci = (int)(i & 1023), co = (int)(i >> 10);
    const float* ws = w + ((size_t)co * (2 * C_) + ci) * 9;
    float gm[3][3];
#pragma unroll
    for (int r = 0; r < 3; ++r)
#pragma unroll
        for (int s = 0; s < 3; ++s) gm[r][s] = ws[r * 3 + s];

    float Gg[4][3];
#pragma unroll
    for (int s = 0; s < 3; ++s) {
        Gg[0][s] = gm[0][s];
        Gg[1][s] = 0.5f * (gm[0][s] + gm[1][s] + gm[2][s]);
        Gg[2][s] = 0.5f * (gm[0][s] - gm[1][s] + gm[2][s]);
        Gg[3][s] = gm[2][s];
    }
#pragma unroll
    for (int r = 0; r < 4; ++r) {
        float a = Gg[r][0], bb = Gg[r][1], c = Gg[r][2];
        float u[4] = {a, 0.5f * (a + bb + c), 0.5f * (a - bb + c), c};
#pragma unroll
        for (int s = 0; s < 4; ++s) {
            int p = r * 4 + s;
            U[((size_t)p * C_ + co) * (2 * C_) + ci] = __float2half_rn(u[s]);
        }
    }
}

// ---------------------------------------------------------------------------
// Winograd GEMM: M_p[tile][co] = V_p[tile,:] @ U_p[co,:]^T. grid (4,1,768)
// ---------------------------------------------------------------------------
__global__ void __launch_bounds__(256, 1) k_wino(const __half* __restrict__ V,
                                                 const __half* __restrict__ U,
                                                 float* __restrict__ M32) {
    GEMM_PRE();
    int z = blockIdx.z, j = z >> 8, p = (z >> 4) & 15, b = z & 15;
    int cb0 = blockIdx.x * 128;
    const __half* arow = V + ((size_t)(j * 16 + p)) * VPT
                           + ((size_t)b * 256 + t) * 1024;
    const __half* brow = U + ((size_t)p * C_ + cb0 + (t & 127)) * (2 * C_);
    float* Mb = M32 + ((size_t)(j * 16 + p)) * MPT + (size_t)b * 256 * 512;

    auto issue = [&](int it) {
        uint32_t da = sAs + (it & 3) * ASTG + t * 48;
        const __half* pa = arow + it * 16;
        cpa16(da, pa, 16); cpa16(da + 16, pa + 8, 16);
        if (t < 128) {
            uint32_t db = sBs + (it & 3) * BSTG + t * 48;
            const __half* pb = brow + it * 16;
            cpa16(db, pb, 16); cpa16(db + 16, pb + 8, 16);
        }
    };

    ZERO_ACC(acc);
    GEMM_PIPE((2 * C_) / 16, issue, acc);

#pragma unroll
    for (int mt = 0; mt < 4; ++mt)
#pragma unroll
        for (int nt = 0; nt < 8; ++nt) {
            int row = wm + mt * 16 + g;
            int col = cb0 + wn + nt * 8 + tg * 2;
            *(float2*)(Mb + (size_t)row * 512 + col)       = make_float2(acc[mt][nt][0], acc[mt][nt][1]);
            *(float2*)(Mb + (size_t)(row + 8) * 512 + col) = make_float2(acc[mt][nt][2], acc[mt][nt][3]);
        }
}

// ---------------------------------------------------------------------------
// Output transform core: load 16 M points for (tile, 2 co), A^T M A
// ---------------------------------------------------------------------------
__device__ __forceinline__ void otrans_core(const float2* M2, size_t jbase,
                                            int tile, int b, int t,
                                            float2 (&y)[2][2]) {
    float2 m[16];
#pragma unroll
    for (int p = 0; p < 16; ++p)
        m[p] = M2[jbase + (size_t)p * (MPT / 2)
                  + ((size_t)b * 256 + tile) * 256 + t];
    float2 tmp[2][4];
#pragma unroll
    for (int c = 0; c < 4; ++c) {
        tmp[0][c].x = m[c].x + m[4 + c].x + m[8 + c].x;
        tmp[0][c].y = m[c].y + m[4 + c].y + m[8 + c].y;
        tmp[1][c].x = m[4 + c].x - m[8 + c].x - m[12 + c].x;
        tmp[1][c].y = m[4 + c].y - m[8 + c].y - m[12 + c].y;
    }
#pragma unroll
    for (int r = 0; r < 2; ++r) {
        y[r][0].x = tmp[r][0].x + tmp[r][1].x + tmp[r][2].x;
        y[r][0].y = tmp[r][0].y + tmp[r][1].y + tmp[r][2].y;
        y[r][1].x = tmp[r][1].x - tmp[r][2].x - tmp[r][3].x;
        y[r][1].y = tmp[r][1].y - tmp[r][2].y - tmp[r][3].y;
    }
}

// Fusion output transform -> fp16 aT[p][co]. grid (256, 48=j*16+b)
__global__ void k_otransF(const float* __restrict__ M32,
                          const float* __restrict__ bias,
                          __half* __restrict__ aT) {
    int tile = blockIdx.x;
    int zb = blockIdx.y, j = zb >> 4, b = zb & 15;
    int t = threadIdx.x;
    int ty = tile >> 4, tx = tile & 15;

    float2 y[2][2];
    otrans_core((const float2*)M32, ((size_t)j * 16) * (MPT / 2), tile, b, t, y);
    float2 bv = ((const float2*)bias)[t];
    __half2* out = (__half2*)(aT + (size_t)j * TSZ + (size_t)b * N_ * C_);
#pragma unroll
    for (int r = 0; r < 2; ++r) {
        int p0 = (2 * ty + r) * HW + 2 * tx;
        out[(size_t)p0 * 256 + t]       = __floats2half2_rn(y[r][0].x + bv.x, y[r][0].y + bv.y);
        out[(size_t)(p0 + 1) * 256 + t] = __floats2half2_rn(y[r][1].x + bv.x, y[r][1].y + bv.y);
    }
}

// Final output transform -> fp32 out [s][b][co][p]. grid (256, 48=s*16+b)
__global__ void k_otransO(const float* __restrict__ M32,
                          const float* __restrict__ bias,
                          float* __restrict__ Y) {
    int tile = blockIdx.x;
    int zb = blockIdx.y, s = zb >> 4, b = zb & 15;
    int t = threadIdx.x;
    int ty = tile >> 4, tx = tile & 15;

    float2 y[2][2];
    otrans_core((const float2*)M32, ((size_t)s * 16) * (MPT / 2), tile, b, t, y);
    float2 bv = ((const float2*)bias)[t];
    float* out = Y + (size_t)s * TSZ + (size_t)b * C_ * N_;
    int co0 = 2 * t;
#pragma unroll
    for (int r = 0; r < 2; ++r) {
        int p0 = (2 * ty + r) * HW + 2 * tx;
        out[(size_t)co0 * N_ + p0]           = y[r][0].x + bv.x;
        out[(size_t)co0 * N_ + p0 + 1]       = y[r][1].x + bv.x;
        out[(size_t)(co0 + 1) * N_ + p0]     = y[r][0].y + bv.y;
        out[(size_t)(co0 + 1) * N_ + p0 + 1] = y[r][1].y + bv.y;
    }
}

// ---------------------------------------------------------------------------
// k_gemmRU_all: 3 fused reset+update GEMMs, M=1024 (r|u), 256x128 tiles.
// ---------------------------------------------------------------------------
__global__ void __launch_bounds__(256, 1) k_gemmRU_all(
        const __half* __restrict__ Wru, const __half* __restrict__ aT,
        const __half* __restrict__ exT, const __half* __restrict__ qT,
        const __half* __restrict__ q1T,
        float* __restrict__ hex, float* __restrict__ hq, float* __restrict__ hq1,
        const float* __restrict__ b_r, const float* __restrict__ b_u,
        __half* __restrict__ rhT, float* __restrict__ u) {
    GEMM_PRE();
    int z = blockIdx.z, j = z >> 4, b = z & 15;
    int co0 = blockIdx.y * 256, p0 = blockIdx.x * 128;
    const __half* hTj = sel3(j, exT, qT, q1T);
    const __half* arow = Wru + (size_t)(co0 + t) * (2 * C_);
    const __half* xrow = aT + (size_t)j * TSZ + (size_t)b * N_ * C_ + (size_t)(p0 + (t & 127)) * C_;
    const __half* hrow = hTj + (size_t)b * N_ * C_ + (size_t)(p0 + (t & 127)) * C_;

    auto issue = [&](int it) {
        int ci0 = it * 16;
        uint32_t da = sAs + (it & 3) * ASTG + t * 48;
        const __half* pa = arow + ci0;
        cpa16(da, pa, 16); cpa16(da + 16, pa + 8, 16);
        if (t < 128) {
            uint32_t db = sBs + (it & 3) * BSTG + t * 48;
            const __half* pb = (ci0 < C_) ? (xrow + ci0) : (hrow + ci0 - C_);
            cpa16(db, pb, 16); cpa16(db + 16, pb + 8, 16);
        }
    };

    ZERO_ACC(acc);
    GEMM_PIPE((2 * C_) / 16, issue, acc);

    bool isR = co0 < C_;
    if (isR) {
        const float* hb = sel3cf(j, hex, hq, hq1) + (size_t)b * C_ * N_;
        __half* rh = rhT + (size_t)j * TSZ + (size_t)b * N_ * C_;
#pragma unroll
        for (int mt = 0; mt < 4; ++mt)
#pragma unroll
            for (int nt = 0; nt < 8; ++nt) {
                int row = co0 + wm + mt * 16 + g;
                int col = p0 + wn + nt * 8 + tg * 2;
                float bv0 = b_r[row], bv1 = b_r[row + 8];
                float o0 = sigm(acc[mt][nt][0] + bv0) * hb[(size_t)row * N_ + col];
                float o1 = sigm(acc[mt][nt][1] + bv0) * hb[(size_t)row * N_ + col + 1];
                float o2 = sigm(acc[mt][nt][2] + bv1) * hb[(size_t)(row + 8) * N_ + col];
                float o3 = sigm(acc[mt][nt][3] + bv1) * hb[(size_t)(row + 8) * N_ + col + 1];
                rh[(size_t)col * C_ + row]           = __float2half_rn(o0);
                rh[(size_t)(col + 1) * C_ + row]     = __float2half_rn(o1);
                rh[(size_t)col * C_ + row + 8]       = __float2half_rn(o2);
                rh[(size_t)(col + 1) * C_ + row + 8] = __float2half_rn(o3);
            }
    } else {
        int rbase = co0 - C_;
        float* ub = u + (size_t)j * TSZ + (size_t)b * C_ * N_;
#pragma unroll
        for (int mt = 0; mt < 4; ++mt)
#pragma unroll
            for (int nt = 0; nt < 8; ++nt) {
                int row = rbase + wm + mt * 16 + g;
                int col = p0 + wn + nt * 8 + tg * 2;
                float bv0 = b_u[row], bv1 = b_u[row + 8];
                *(float2*)(ub + (size_t)row * N_ + col) =
                    make_float2(sigm(acc[mt][nt][0] + bv0), sigm(acc[mt][nt][1] + bv0));
                *(float2*)(ub + (size_t)(row + 8) * N_ + col) =
                    make_float2(sigm(acc[mt][nt][2] + bv1), sigm(acc[mt][nt][3] + bv1));
            }
    }
}

// ---------------------------------------------------------------------------
// k_gemmCAND_all + fused GRU update: c = tanh(Wc@[x;r*h]+b);
// h = h(1-u) + c*u; writes fp32 h and both fp16 mirrors. grid (8,2,48)
// ---------------------------------------------------------------------------
__global__ void __launch_bounds__(256, 1) k_gemmCAND_all(
        const __half* __restrict__ Wc, const __half* __restrict__ aT,
        const __half* __restrict__ rhT, const float* __restrict__ bias,
        const float* __restrict__ u,
        float* __restrict__ hex, float* __restrict__ hq, float* __restrict__ hq1,
        __half* __restrict__ n16_0, __half* __restrict__ n16_1, __half* __restrict__ n16_2,
        __half* __restrict__ nT_0, __half* __restrict__ nT_1, __half* __restrict__ nT_2) {
    GEMM_PRE();
    int z = blockIdx.z, j = z >> 4, b = z & 15;
    int co0 = blockIdx.y * 256, p0 = blockIdx.x * 128;
    const __half* arow  = Wc + (size_t)(co0 + t) * (2 * C_);
    const __half* xrow  = aT  + (size_t)j * TSZ + (size_t)b * N_ * C_ + (size_t)(p0 + (t & 127)) * C_;
    const __half* rhrow = rhT + (size_t)j * TSZ + (size_t)b * N_ * C_ + (size_t)(p0 + (t & 127)) * C_;

    auto issue = [&](int it) {
        int ci0 = it * 16;
        uint32_t da = sAs + (it & 3) * ASTG + t * 48;
        const __half* pa = arow + ci0;
        cpa16(da, pa, 16); cpa16(da + 16, pa + 8, 16);
        if (t < 128) {
            uint32_t db = sBs + (it & 3) * BSTG + t * 48;
            const __half* pb = (ci0 < C_) ? (xrow + ci0) : (rhrow + ci0 - C_);
            cpa16(db, pb, 16); cpa16(db + 16, pb + 8, 16);
        }
    };

    ZERO_ACC(acc);
    GEMM_PIPE((2 * C_) / 16, issue, acc);

    float* hb  = sel3f(j, hex, hq, hq1) + (size_t)b * C_ * N_;
    const float* ub = u + (size_t)j * TSZ + (size_t)b * C_ * N_;
    __half* on = sel3h(j, n16_0, n16_1, n16_2) + (size_t)b * C_ * N_;
    __half* ot = sel3h(j, nT_0, nT_1, nT_2)    + (size_t)b * N_ * C_;

#pragma unroll
    for (int mt = 0; mt < 4; ++mt)
#pragma unroll
        for (int nt = 0; nt < 8; ++nt) {
            int row = co0 + wm + mt * 16 + g;
            int col = p0 + wn + nt * 8 + tg * 2;
            float bv0 = bias[row], bv1 = bias[row + 8];
            float cv[4] = {tanhf(acc[mt][nt][0] + bv0), tanhf(acc[mt][nt][1] + bv0),
                           tanhf(acc[mt][nt][2] + bv1), tanhf(acc[mt][nt][3] + bv1)};
            int rows[2] = {row, row + 8};
#pragma unroll
            for (int rr = 0; rr < 2; ++rr) {
                size_t i0 = (size_t)rows[rr] * N_ + col;
                float2 hv = *(float2*)(hb + i0);
                float2 uv = *(const float2*)(ub + i0);
                float h0 = hv.x * (1.f - uv.x) + cv[2 * rr]     * uv.x;
                float h1 = hv.y * (1.f - uv.y) + cv[2 * rr + 1] * uv.y;
                *(float2*)(hb + i0) = make_float2(h0, h1);
                *(__half2*)(on + i0) = __floats2half2_rn(h0, h1);
                ot[(size_t)col * C_ + rows[rr]]       = __float2half_rn(h0);
                ot[(size_t)(col + 1) * C_ + rows[rr]] = __float2half_rn(h1);
            }
        }
}

// ---------------------------------------------------------------------------
// Prep kernels
// ---------------------------------------------------------------------------
__global__ void k_prep_g(const float* __restrict__ wr, const float* __restrict__ wu,
                         const float* __restrict__ wc,
                         __half* __restrict__ oru, __half* __restrict__ oc) {
    size_t i = (size_t)blockIdx.x * 256 + threadIdx.x;
    size_t half = (size_t)C_ * 2 * C_;
    if (i < half) oru[i] = __float2half_rn(wr[i]);
    else if (i < 2 * half) oru[i] = __float2half_rn(wu[i - half]);
    else if (i < 3 * half) oc[i - 2 * half] = __float2half_rn(wc[i - 2 * half]);
}

__global__ void k_premirror(
        const float* __restrict__ in1, const float* __restrict__ in2,
        const float* __restrict__ in3,
        float* __restrict__ hex, float* __restrict__ hq, float* __restrict__ hq1,
        __half* __restrict__ m16_0, __half* __restrict__ m16_1, __half* __restrict__ m16_2,
        __half* __restrict__ mT_0, __half* __restrict__ mT_1, __half* __restrict__ mT_2,
        __half* __restrict__ i1T, __half* __restrict__ i2T, __half* __restrict__ i3T) {
    __shared__ float tile[32][33];
    int z = blockIdx.z;
    int tx = threadIdx.x, ty = threadIdx.y;
    int n0 = blockIdx.x * 32, c0 = blockIdx.y * 32;
    if (z < 48) {
        int s = z >> 4, b = z & 15;
        const float* ib = sel3cf(s, in1, in2, in3) + (size_t)b * C_ * N_;
        float* hb = sel3f(s, hex, hq, hq1) + (size_t)b * C_ * N_;
        __half* on = sel3h(s, m16_0, m16_1, m16_2) + (size_t)b * C_ * N_;
        __half* ot = sel3h(s, mT_0, mT_1, mT_2)    + (size_t)b * N_ * C_;
#pragma unroll
        for (int j = 0; j < 4; ++j) {
            size_t idx = (size_t)(c0 + ty + 8 * j) * N_ + n0 + tx;
            float v = ib[idx];
            hb[idx] = v;
            on[idx] = __float2half_rn(v);
            tile[ty + 8 * j][tx] = v;
        }
        __syncthreads();
#pragma unroll
        for (int j = 0; j < 4; ++j)
            ot[(size_t)(n0 + ty + 8 * j) * C_ + c0 + tx] = __float2half_rn(tile[tx][ty + 8 * j]);
    } else {
        int s = (z - 48) >> 4, b = (z - 48) & 15;
        const float* ib = sel3cf(s, in1, in2, in3) + (size_t)b * C_ * N_;
        __half* ot = sel3h(s, i1T, i2T, i3T) + (size_t)b * N_ * C_;
#pragma unroll
        for (int j = 0; j < 4; ++j)
            tile[ty + 8 * j][tx] = ib[(size_t)(c0 + ty + 8 * j) * N_ + n0 + tx];
        __syncthreads();
#pragma unroll
        for (int j = 0; j < 4; ++j)
            ot[(size_t)(n0 + ty + 8 * j) * C_ + c0 + tx] = __float2half_rn(tile[tx][ty + 8 * j]);
    }
}

// ---------------------------------------------------------------------------
// Host orchestration
// ---------------------------------------------------------------------------
extern "C" void kernel_launch(void* const* d_in, const int* in_sizes, int n_in,
                              void* d_out, int out_size) {
    const float* in1      = (const float*)d_in[0];
    const float* in2      = (const float*)d_in[1];
    const float* in3      = (const float*)d_in[2];
    const float* w_fusion = (const float*)d_in[3];
    const float* b_fusion = (const float*)d_in[4];
    const float* w_out    = (const float*)d_in[5];
    const float* b_out    = (const float*)d_in[6];
    const float* w_reset  = (const float*)d_in[7];
    const float* b_reset  = (const float*)d_in[8];
    const float* w_update = (const float*)d_in[9];
    const float* b_update = (const float*)d_in[10];
    const float* w_cand   = (const float*)d_in[11];
    const float* b_cand   = (const float*)d_in[12];
    float* out = (float*)d_out;

    cudaFuncSetAttribute(k_scores_all,   cudaFuncAttributeMaxDynamicSharedMemorySize, SMEM_DYN);
    cudaFuncSetAttribute(k_attmmT_all,   cudaFuncAttributeMaxDynamicSharedMemorySize, SMEM_DYN);
    cudaFuncSetAttribute(k_wino,         cudaFuncAttributeMaxDynamicSharedMemorySize, SMEM_DYN);
    cudaFuncSetAttribute(k_gemmRU_all,   cudaFuncAttributeMaxDynamicSharedMemorySize, SMEM_DYN);
    cudaFuncSetAttribute(k_gemmCAND_all, cudaFuncAttributeMaxDynamicSharedMemorySize, SMEM_DYN);

    float *S, *ex, *q, *q1, *u, *M32;
    __half *P16, *OT, *aT, *rhT, *in1T, *in2T, *in3T, *V, *Uf, *Uo;
    __half *wru16, *wc16;
    __half *m16a[3], *m16b[3], *mTa[3], *mTb[3];
    cudaGetSymbolAddress((void**)&S,    g_S);
    cudaGetSymbolAddress((void**)&ex,   g_ex);
    cudaGetSymbolAddress((void**)&q,    g_q);
    cudaGetSymbolAddress((void**)&q1,   g_q1);
    cudaGetSymbolAddress((void**)&u,    g_u);
    cudaGetSymbolAddress((void**)&M32,  g_M32);
    cudaGetSymbolAddress((void**)&P16,  g_P16);
    cudaGetSymbolAddress((void**)&OT,   g_OT);
    cudaGetSymbolAddress((void**)&aT,   g_aT);
    cudaGetSymbolAddress((void**)&rhT,  g_rhT);
    cudaGetSymbolAddress((void**)&V,    g_V);
    cudaGetSymbolAddress((void**)&Uf,   g_Uf);
    cudaGetSymbolAddress((void**)&Uo,   g_Uo);
    cudaGetSymbolAddress((void**)&in1T, g_in1T16);
    cudaGetSymbolAddress((void**)&in2T, g_in2T16);
    cudaGetSymbolAddress((void**)&in3T, g_in3T16);
    cudaGetSymbolAddress((void**)&wru16, g_wru16);
    cudaGetSymbolAddress((void**)&wc16, g_wc16);
    cudaGetSymbolAddress((void**)&m16a[0], g_ex16a);
    cudaGetSymbolAddress((void**)&m16a[1], g_q16a);
    cudaGetSymbolAddress((void**)&m16a[2], g_q116a);
    cudaGetSymbolAddress((void**)&m16b[0], g_ex16b);
    cudaGetSymbolAddress((void**)&m16b[1], g_q16b);
    cudaGetSymbolAddress((void**)&m16b[2], g_q116b);
    cudaGetSymbolAddress((void**)&mTa[0], g_exT16a);
    cudaGetSymbolAddress((void**)&mTa[1], g_qT16a);
    cudaGetSymbolAddress((void**)&mTa[2], g_q1T16a);
    cudaGetSymbolAddress((void**)&mTb[0], g_exT16b);
    cudaGetSymbolAddress((void**)&mTb[1], g_qT16b);
    cudaGetSymbolAddress((void**)&mTb[2], g_q1T16b);

    const int GG = (int)((3 * (size_t)C_ * 2 * C_ + 255) / 256);

    // prep (4 launches)
    k_prep_g<<<GG, 256>>>(w_reset, w_update, w_cand, wru16, wc16);
    k_wt_wino<<<2048, 256>>>(w_fusion, Uf);
    k_wt_wino<<<2048, 256>>>(w_out, Uo);
    k_premirror<<<dim3(32, 16, 96), dim3(32, 8)>>>(
        in1, in2, in3, ex, q, q1,
        m16a[0], m16a[1], m16a[2], mTa[0], mTa[1], mTa[2],
        in1T, in2T, in3T);

    __half** cur16 = m16a;  __half** curT = mTa;
    __half** nw16  = m16b;  __half** nwT  = mTb;

    for (int round = 0; round < 5; ++round) {
        k_scores_all<<<dim3(8, 4, 96), 256, SMEM_DYN>>>(curT[0], curT[1], curT[2], S);
        k_softmax_all<<<6 * B_ * N_, 256>>>(S, P16);
        k_attmmT_all<<<dim3(4, 4, 96), 256, SMEM_DYN>>>(P16, cur16[0], cur16[1], cur16[2], OT);

        // fusion convs via Winograd F(2x2,3x3)
        k_dtransF<<<dim3(256, 48), 256>>>(OT, V);
        k_wino<<<dim3(4, 1, 768), 256, SMEM_DYN>>>(V, Uf, M32);
        k_otransF<<<dim3(256, 48), 256>>>(M32, b_fusion, aT);

        k_gemmRU_all<<<dim3(8, 4, 48), 256, SMEM_DYN>>>(
            wru16, aT, curT[0], curT[1], curT[2], ex, q, q1,
            b_reset, b_update, rhT, u);
        // CAND + fused GRU state update + mirror emission
        k_gemmCAND_all<<<dim3(8, 2, 48), 256, SMEM_DYN>>>(
            wc16, aT, rhT, b_cand, u, ex, q, q1,
            nw16[0], nw16[1], nw16[2], nwT[0], nwT[1], nwT[2]);

        __half** t16 = cur16; cur16 = nw16; nw16 = t16;
        __half** tT  = curT;  curT  = nwT;  nwT  = tT;
    }

    // final output convs via Winograd
    k_dtransO<<<dim3(256, 48), 256>>>(curT[0], curT[1], curT[2],
                                      in1T, in2T, in3T, V);
    k_wino<<<dim3(4, 1, 768), 256, SMEM_DYN>>>(V, Uo, M32);
    k_otransO<<<dim3(256, 48), 256>>>(M32, b_out, out);
}

// round 16
// speedup vs baseline: 1.0201x; 1.0201x over previous
#include <cuda_runtime.h>
#include <cuda_fp16.h>
#include <math.h>
#include <stdint.h>

// ---------------------------------------------------------------------------
// Problem constants
// ---------------------------------------------------------------------------
#define B_  16
#define C_  512
#define N_  1024
#define HW  32
#define SPITCH 12                      // smem row stride in u32 (48B) - conflict-free
#define NSTG 4                         // pipeline stages
#define ASTG (256 * SPITCH * 4)        // 12288 B per A stage (256 rows)
#define BSTG (128 * SPITCH * 4)        // 6144 B per B stage (128 rows)
#define SMEM_DYN (NSTG * (ASTG + BSTG))   // 73728 B

static constexpr size_t TSZ  = (size_t)B_ * C_ * N_;
static constexpr size_t SSZ  = (size_t)B_ * N_ * N_;
static constexpr size_t VPT  = (size_t)16 * 256 * 1024;   // V halfs per (j,point)
static constexpr size_t MPT  = (size_t)16 * 256 * 512;    // M elems per (j,point)

// ---------------------------------------------------------------------------
// Scratch (static device globals; no allocation anywhere)
// ---------------------------------------------------------------------------
__device__ float g_S [6 * SSZ];
__device__ float g_ex[TSZ], g_q [TSZ], g_q1[TSZ];
__device__ float g_u [3 * TSZ], g_c [3 * TSZ];
__device__ float g_M32[(size_t)3 * 16 * MPT];      // fp32 M (final conv path)

__device__ __align__(128) __half g_M16[(size_t)3 * 16 * MPT];   // fp16 M (fusion path)
__device__ __align__(128) __half g_P16[6 * SSZ];
__device__ __align__(128) __half g_OT [6 * TSZ];   // attention outputs [p][c]
__device__ __align__(128) __half g_aT [3 * TSZ];   // fusion outputs [p][c]
__device__ __align__(128) __half g_rhT[3 * TSZ];
__device__ __align__(128) __half g_V  [(size_t)3 * 16 * VPT];   // winograd data
__device__ __align__(128) __half g_Uf [(size_t)16 * C_ * (2 * C_)]; // transformed wf
__device__ __align__(128) __half g_Uo [(size_t)16 * C_ * (2 * C_)]; // transformed wo
__device__ __align__(128) __half g_ex16a [TSZ], g_q16a [TSZ], g_q116a[TSZ];
__device__ __align__(128) __half g_ex16b [TSZ], g_q16b [TSZ], g_q116b[TSZ];
__device__ __align__(128) __half g_exT16a[TSZ], g_qT16a[TSZ], g_q1T16a[TSZ];
__device__ __align__(128) __half g_exT16b[TSZ], g_qT16b[TSZ], g_q1T16b[TSZ];
__device__ __align__(128) __half g_in1T16[TSZ], g_in2T16[TSZ], g_in3T16[TSZ];
__device__ __align__(128) __half g_wru16[(size_t)(2 * C_) * (2 * C_)];
__device__ __align__(128) __half g_wc16 [(size_t)C_ * (2 * C_)];

// ---------------------------------------------------------------------------
// Helpers
// ---------------------------------------------------------------------------
__device__ __forceinline__ const __half* sel3(int i, const __half* a,
                                              const __half* b, const __half* c) {
    return i == 0 ? a : (i == 1 ? b : c);
}
__device__ __forceinline__ __half* sel3h(int i, __half* a, __half* b, __half* c) {
    return i == 0 ? a : (i == 1 ? b : c);
}
__device__ __forceinline__ float* sel3f(int i, float* a, float* b, float* c) {
    return i == 0 ? a : (i == 1 ? b : c);
}
__device__ __forceinline__ const float* sel3cf(int i, const float* a,
                                               const float* b, const float* c) {
    return i == 0 ? a : (i == 1 ? b : c);
}
__device__ __forceinline__ int pairB(int j) {
    switch (j) { case 0: return 1; case 1: return 2; case 2: return 0;
                 case 3: return 2; case 4: return 0; default: return 1; }
}
__device__ __forceinline__ float sigm(float x) { return 1.f / (1.f + __expf(-x)); }

__device__ __forceinline__ void cpa16(uint32_t dst, const void* src, uint32_t sz) {
    asm volatile("cp.async.ca.shared.global [%0], [%1], 16, %2;"
                 :: "r"(dst), "l"(src), "r"(sz) : "memory");
}
#define CP_COMMIT() asm volatile("cp.async.commit_group;" ::: "memory")
#define CP_WAIT2()  asm volatile("cp.async.wait_group 2;" ::: "memory")

// ---------------------------------------------------------------------------
// fp16 mma.sync microkernel. Block tile 256x128, 8 warps (4m x 2n of 64x64).
// ---------------------------------------------------------------------------
__device__ __forceinline__ void mma16(float* d, const uint32_t* a, uint32_t b0, uint32_t b1) {
    asm volatile(
        "mma.sync.aligned.m16n8k16.row.col.f32.f16.f16.f32 "
        "{%0,%1,%2,%3}, {%4,%5,%6,%7}, {%8,%9}, {%0,%1,%2,%3};\n"
        : "+f"(d[0]), "+f"(d[1]), "+f"(d[2]), "+f"(d[3])
        : "r"(a[0]), "r"(a[1]), "r"(a[2]), "r"(a[3]), "r"(b0), "r"(b1));
}

__device__ __forceinline__ void ldsm4(uint32_t* r, uint32_t addr) {
    asm volatile(
        "ldmatrix.sync.aligned.m8n8.x4.shared.b16 {%0,%1,%2,%3}, [%4];"
        : "=r"(r[0]), "=r"(r[1]), "=r"(r[2]), "=r"(r[3]) : "r"(addr));
}

__device__ __forceinline__ void compute16(uint32_t aB, uint32_t bB,
                                          float (*acc)[8][4], int wm, int wn,
                                          int lane) {
    int lr = lane & 15;
    uint32_t lc = (uint32_t)(lane >> 4) * 16;
    uint32_t a[4][4], b[4][4];
#pragma unroll
    for (int mt = 0; mt < 4; ++mt)
        ldsm4(a[mt], aB + (uint32_t)(wm + mt * 16 + lr) * (SPITCH * 4) + lc);
#pragma unroll
    for (int np = 0; np < 4; ++np)
        ldsm4(b[np], bB + (uint32_t)(wn + np * 16 + lr) * (SPITCH * 4) + lc);
#pragma unroll
    for (int mt = 0; mt < 4; ++mt)
#pragma unroll
        for (int np = 0; np < 4; ++np) {
            mma16(acc[mt][2 * np],     a[mt], b[np][0], b[np][2]);
            mma16(acc[mt][2 * np + 1], a[mt], b[np][1], b[np][3]);
        }
}

#define ZERO_ACC(acc)                                       \
    float acc[4][8][4];                                     \
    _Pragma("unroll")                                       \
    for (int i_ = 0; i_ < 4; ++i_)                          \
        _Pragma("unroll")                                   \
        for (int j_ = 0; j_ < 8; ++j_)                      \
            _Pragma("unroll")                               \
            for (int v_ = 0; v_ < 4; ++v_) acc[i_][j_][v_] = 0.f;

#define GEMM_PRE()                                                           \
    extern __shared__ __align__(1024) char dsm[];                            \
    int t = threadIdx.x, lane = t & 31, wid = t >> 5;                        \
    int wm = (wid & 3) * 64, wn = (wid >> 2) * 64;                           \
    int g = lane >> 2, tg = lane & 3;                                        \
    uint32_t sAs = (uint32_t)__cvta_generic_to_shared(dsm);                  \
    uint32_t sBs = sAs + NSTG * ASTG;                                        \
    (void)g; (void)tg;

#define GEMM_PIPE(KI, ISSUE, acc)                                            \
    for (int s_ = 0; s_ < 3; ++s_) { ISSUE(s_); CP_COMMIT(); }               \
    for (int it_ = 0; it_ < (KI); ++it_) {                                   \
        CP_WAIT2();                                                          \
        __syncthreads();                                                     \
        compute16(sAs + (it_ & 3) * ASTG, sBs + (it_ & 3) * BSTG,            \
                  acc, wm, wn, lane);                                        \
        if (it_ + 3 < (KI)) ISSUE(it_ + 3);                                  \
        CP_COMMIT();                                                         \
    }

// ---------------------------------------------------------------------------
// k_scores_all: 6 logits GEMMs, 256x128 tiles. grid (8,4,96), 256 thr
// ---------------------------------------------------------------------------
__global__ void __launch_bounds__(256, 1) k_scores_all(
        const __half* __restrict__ exT, const __half* __restrict__ qT,
        const __half* __restrict__ q1T, float* __restrict__ S) {
    GEMM_PRE();
    int z = blockIdx.z, j = z >> 4, b = z & 15;
    const __half* A  = sel3(j >> 1,   exT, qT, q1T);
    const __half* Bm = sel3(pairB(j), exT, qT, q1T);
    int n0 = blockIdx.y * 256, m0 = blockIdx.x * 128;
    const __half* arow = A  + (size_t)b * N_ * C_ + (size_t)(n0 + t) * C_;
    const __half* brow = Bm + (size_t)b * N_ * C_ + (size_t)(m0 + (t & 127)) * C_;
    float* Sb = S + (size_t)j * SSZ + (size_t)b * N_ * N_;

    auto issue = [&](int it) {
        uint32_t da = sAs + (it & 3) * ASTG + t * 48;
        const __half* pa = arow + it * 16;
        cpa16(da, pa, 16); cpa16(da + 16, pa + 8, 16);
        if (t < 128) {
            uint32_t db = sBs + (it & 3) * BSTG + t * 48;
            const __half* pb = brow + it * 16;
            cpa16(db, pb, 16); cpa16(db + 16, pb + 8, 16);
        }
    };

    ZERO_ACC(acc);
    GEMM_PIPE(C_ / 16, issue, acc);

#pragma unroll
    for (int mt = 0; mt < 4; ++mt)
#pragma unroll
        for (int nt = 0; nt < 8; ++nt) {
            int row = n0 + wm + mt * 16 + g;
            int col = m0 + wn + nt * 8 + tg * 2;
            *(float2*)(Sb + (size_t)row * N_ + col)       = make_float2(acc[mt][nt][0], acc[mt][nt][1]);
            *(float2*)(Sb + (size_t)(row + 8) * N_ + col) = make_float2(acc[mt][nt][2], acc[mt][nt][3]);
        }
}

// ---------------------------------------------------------------------------
// Row softmax over all 6 matrices. grid 6*B_*N_, 256 thr
// ---------------------------------------------------------------------------
__global__ void __launch_bounds__(256) k_softmax_all(const float* __restrict__ S,
                                                     __half* __restrict__ P) {
    const float* row = S + (size_t)blockIdx.x * N_;
    __half*      out = P + (size_t)blockIdx.x * N_;
    int t = threadIdx.x;
    float4 v = *(const float4*)(row + 4 * t);
    __shared__ float red[8];

    float m = fmaxf(fmaxf(v.x, v.y), fmaxf(v.z, v.w));
#pragma unroll
    for (int o = 16; o; o >>= 1) m = fmaxf(m, __shfl_xor_sync(0xffffffffu, m, o));
    if ((t & 31) == 0) red[t >> 5] = m;
    __syncthreads();
    float mx = red[0];
#pragma unroll
    for (int i = 1; i < 8; ++i) mx = fmaxf(mx, red[i]);
    __syncthreads();

    v.x = __expf(v.x - mx); v.y = __expf(v.y - mx);
    v.z = __expf(v.z - mx); v.w = __expf(v.w - mx);
    float s = v.x + v.y + v.z + v.w;
#pragma unroll
    for (int o = 16; o; o >>= 1) s += __shfl_xor_sync(0xffffffffu, s, o);
    if ((t & 31) == 0) red[t >> 5] = s;
    __syncthreads();
    float tot = red[0];
#pragma unroll
    for (int i = 1; i < 8; ++i) tot += red[i];
    float inv = 1.f / tot;

    *(__half2*)(out + 4 * t)     = __floats2half2_rn(v.x * inv, v.y * inv);
    *(__half2*)(out + 4 * t + 2) = __floats2half2_rn(v.z * inv, v.w * inv);
}

// ---------------------------------------------------------------------------
// k_attmmT_all: 6 attention-output GEMMs, fp16 [p][c], 256x128 tiles.
// ---------------------------------------------------------------------------
__global__ void __launch_bounds__(256, 1) k_attmmT_all(
        const __half* __restrict__ P,
        const __half* __restrict__ ex16, const __half* __restrict__ q16,
        const __half* __restrict__ q116, __half* __restrict__ OT) {
    GEMM_PRE();
    int z = blockIdx.z, j = z >> 4, b = z & 15;
    const __half* Bn = sel3(pairB(j), ex16, q16, q116);
    int n0 = blockIdx.y * 256, c0 = blockIdx.x * 128;
    const __half* arow = P  + (size_t)j * SSZ + (size_t)b * N_ * N_ + (size_t)(n0 + t) * N_;
    const __half* brow = Bn + (size_t)b * C_ * N_ + (size_t)(c0 + (t & 127)) * N_;
    __half* Ob = OT + (size_t)j * TSZ + (size_t)b * N_ * C_;

    auto issue = [&](int it) {
        uint32_t da = sAs + (it & 3) * ASTG + t * 48;
        const __half* pa = arow + it * 16;
        cpa16(da, pa, 16); cpa16(da + 16, pa + 8, 16);
        if (t < 128) {
            uint32_t db = sBs + (it & 3) * BSTG + t * 48;
            const __half* pb = brow + it * 16;
            cpa16(db, pb, 16); cpa16(db + 16, pb + 8, 16);
        }
    };

    ZERO_ACC(acc);
    GEMM_PIPE(N_ / 16, issue, acc);

#pragma unroll
    for (int mt = 0; mt < 4; ++mt)
#pragma unroll
        for (int nt = 0; nt < 8; ++nt) {
            int row = n0 + wm + mt * 16 + g;
            int col = c0 + wn + nt * 8 + tg * 2;
            *(__half2*)(Ob + (size_t)row * C_ + col) =
                __floats2half2_rn(acc[mt][nt][0], acc[mt][nt][1]);
            *(__half2*)(Ob + (size_t)(row + 8) * C_ + col) =
                __floats2half2_rn(acc[mt][nt][2], acc[mt][nt][3]);
        }
}

// ---------------------------------------------------------------------------
// Winograd data transform core: two [p][c] fp16 sources -> V.
// ---------------------------------------------------------------------------
__device__ __forceinline__ void dtrans_core(const __half2* x0, const __half2* x1,
                                            __half2* V2, size_t base,
                                            int tile, int b, int t) {
    int ty = tile >> 4, tx = tile & 15;
#pragma unroll
    for (int cc = 0; cc < 2; ++cc) {
        const __half2* src = cc ? x1 : x0;
        int ci2 = t + 256 * cc;
        float lo[4][4], hi[4][4];
#pragma unroll
        for (int r = 0; r < 4; ++r) {
            int iy = 2 * ty - 1 + r;
#pragma unroll
            for (int s = 0; s < 4; ++s) {
                int ix = 2 * tx - 1 + s;
                float2 v = make_float2(0.f, 0.f);
                if ((unsigned)iy < HW && (unsigned)ix < HW)
                    v = __half22float2(src[(size_t)(iy * HW + ix) * 256 + t]);
                lo[r][s] = v.x; hi[r][s] = v.y;
            }
        }
        float tl[4][4], th[4][4];
#pragma unroll
        for (int s = 0; s < 4; ++s) {
            tl[0][s] = lo[0][s] - lo[2][s];  th[0][s] = hi[0][s] - hi[2][s];
            tl[1][s] = lo[1][s] + lo[2][s];  th[1][s] = hi[1][s] + hi[2][s];
            tl[2][s] = lo[2][s] - lo[1][s];  th[2][s] = hi[2][s] - hi[1][s];
            tl[3][s] = lo[1][s] - lo[3][s];  th[3][s] = hi[1][s] - hi[3][s];
        }
#pragma unroll
        for (int r = 0; r < 4; ++r) {
            float vl[4], vh[4];
            vl[0] = tl[r][0] - tl[r][2];  vh[0] = th[r][0] - th[r][2];
            vl[1] = tl[r][1] + tl[r][2];  vh[1] = th[r][1] + th[r][2];
            vl[2] = tl[r][2] - tl[r][1];  vh[2] = th[r][2] - th[r][1];
            vl[3] = tl[r][1] - tl[r][3];  vh[3] = th[r][1] - th[r][3];
#pragma unroll
            for (int c = 0; c < 4; ++c) {
                int p = r * 4 + c;
                V2[base + (size_t)p * (VPT / 2)
                   + ((size_t)b * 256 + tile) * 512 + ci2] = __floats2half2_rn(vl[c], vh[c]);
            }
        }
    }
}

// Fusion-conv data transform: sources = OT pair. grid (256, 48=j*16+b)
__global__ void k_dtransF(const __half* __restrict__ OT, __half* __restrict__ V) {
    int tile = blockIdx.x;
    int zb = blockIdx.y, j = zb >> 4, b = zb & 15;
    const __half2* x0 = (const __half2*)(OT + (size_t)(2 * j)     * TSZ + (size_t)b * N_ * C_);
    const __half2* x1 = (const __half2*)(OT + (size_t)(2 * j + 1) * TSZ + (size_t)b * N_ * C_);
    dtrans_core(x0, x1, (__half2*)V, ((size_t)j * 16) * (VPT / 2), tile, b, threadIdx.x);
}

// Final-conv data transform: sources = [stateT ; inT]. grid (256, 48=s*16+b)
__global__ void k_dtransO(const __half* __restrict__ exT, const __half* __restrict__ qT,
                          const __half* __restrict__ q1T,
                          const __half* __restrict__ i1T, const __half* __restrict__ i2T,
                          const __half* __restrict__ i3T, __half* __restrict__ V) {
    int tile = blockIdx.x;
    int zb = blockIdx.y, s = zb >> 4, b = zb & 15;
    const __half2* x0 = (const __half2*)(sel3(s, exT, qT, q1T)   + (size_t)b * N_ * C_);
    const __half2* x1 = (const __half2*)(sel3(s, i1T, i2T, i3T) + (size_t)b * N_ * C_);
    dtrans_core(x0, x1, (__half2*)V, ((size_t)s * 16) * (VPT / 2), tile, b, threadIdx.x);
}

// ---------------------------------------------------------------------------
// Winograd weight transform: U_p[co][ci] from original fp32 weights [co][ci][3][3]
// grid 2048, 256 thr
// ---------------------------------------------------------------------------
__global__ void k_wt_wino(const float* __restrict__ w, __half* __restrict__ U) {
    size_t i = (size_t)blockIdx.x * 256 + threadIdx.x;
    int ci = (int)(i & 1023), co = (int)(i >> 10);
    const float* ws = w + ((size_t)co * (2 * C_) + ci) * 9;
    float gm[3][3];
#pragma unroll
    for (int r = 0; r < 3; ++r)
#pragma unroll
        for (int s = 0; s < 3; ++s) gm[r][s] = ws[r * 3 + s];

    float Gg[4][3];
#pragma unroll
    for (int s = 0; s < 3; ++s) {
        Gg[0][s] = gm[0][s];
        Gg[1][s] = 0.5f * (gm[0][s] + gm[1][s] + gm[2][s]);
        Gg[2][s] = 0.5f * (gm[0][s] - gm[1][s] + gm[2][s]);
        Gg[3][s] = gm[2][s];
    }
#pragma unroll
    for (int r = 0; r < 4; ++r) {
        float a = Gg[r][0], bb = Gg[r][1], c = Gg[r][2];
        float u[4] = {a, 0.5f * (a + bb + c), 0.5f * (a - bb + c), c};
#pragma unroll
        for (int s = 0; s < 4; ++s) {
            int p = r * 4 + s;
            U[((size_t)p * C_ + co) * (2 * C_) + ci] = __float2half_rn(u[s]);
        }
    }
}

// ---------------------------------------------------------------------------
// Winograd GEMM (fp32 M output, final-conv path). grid (4,1,768)
// ---------------------------------------------------------------------------
__global__ void __launch_bounds__(256, 1) k_wino(const __half* __restrict__ V,
                                                 const __half* __restrict__ U,
                                                 float* __restrict__ M32) {
    GEMM_PRE();
    int z = blockIdx.z, j = z >> 8, p = (z >> 4) & 15, b = z & 15;
    int cb0 = blockIdx.x * 128;
    const __half* arow = V + ((size_t)(j * 16 + p)) * VPT
                           + ((size_t)b * 256 + t) * 1024;
    const __half* brow = U + ((size_t)p * C_ + cb0 + (t & 127)) * (2 * C_);
    float* Mb = M32 + ((size_t)(j * 16 + p)) * MPT + (size_t)b * 256 * 512;

    auto issue = [&](int it) {
        uint32_t da = sAs + (it & 3) * ASTG + t * 48;
        const __half* pa = arow + it * 16;
        cpa16(da, pa, 16); cpa16(da + 16, pa + 8, 16);
        if (t < 128) {
            uint32_t db = sBs + (it & 3) * BSTG + t * 48;
            const __half* pb = brow + it * 16;
            cpa16(db, pb, 16); cpa16(db + 16, pb + 8, 16);
        }
    };

    ZERO_ACC(acc);
    GEMM_PIPE((2 * C_) / 16, issue, acc);

#pragma unroll
    for (int mt = 0; mt < 4; ++mt)
#pragma unroll
        for (int nt = 0; nt < 8; ++nt) {
            int row = wm + mt * 16 + g;
            int col = cb0 + wn + nt * 8 + tg * 2;
            *(float2*)(Mb + (size_t)row * 512 + col)       = make_float2(acc[mt][nt][0], acc[mt][nt][1]);
            *(float2*)(Mb + (size_t)(row + 8) * 512 + col) = make_float2(acc[mt][nt][2], acc[mt][nt][3]);
        }
}

// ---------------------------------------------------------------------------
// Winograd GEMM (fp16 M output, fusion-conv path). grid (4,1,768)
// ---------------------------------------------------------------------------
__global__ void __launch_bounds__(256, 1) k_winoF(const __half* __restrict__ V,
                                                  const __half* __restrict__ U,
                                                  __half* __restrict__ M16) {
    GEMM_PRE();
    int z = blockIdx.z, j = z >> 8, p = (z >> 4) & 15, b = z & 15;
    int cb0 = blockIdx.x * 128;
    const __half* arow = V + ((size_t)(j * 16 + p)) * VPT
                           + ((size_t)b * 256 + t) * 1024;
    const __half* brow = U + ((size_t)p * C_ + cb0 + (t & 127)) * (2 * C_);
    __half* Mb = M16 + ((size_t)(j * 16 + p)) * MPT + (size_t)b * 256 * 512;

    auto issue = [&](int it) {
        uint32_t da = sAs + (it & 3) * ASTG + t * 48;
        const __half* pa = arow + it * 16;
        cpa16(da, pa, 16); cpa16(da + 16, pa + 8, 16);
        if (t < 128) {
            uint32_t db = sBs + (it & 3) * BSTG + t * 48;
            const __half* pb = brow + it * 16;
            cpa16(db, pb, 16); cpa16(db + 16, pb + 8, 16);
        }
    };

    ZERO_ACC(acc);
    GEMM_PIPE((2 * C_) / 16, issue, acc);

#pragma unroll
    for (int mt = 0; mt < 4; ++mt)
#pragma unroll
        for (int nt = 0; nt < 8; ++nt) {
            int row = wm + mt * 16 + g;
            int col = cb0 + wn + nt * 8 + tg * 2;
            *(__half2*)(Mb + (size_t)row * 512 + col) =
                __floats2half2_rn(acc[mt][nt][0], acc[mt][nt][1]);
            *(__half2*)(Mb + (size_t)(row + 8) * 512 + col) =
                __floats2half2_rn(acc[mt][nt][2], acc[mt][nt][3]);
        }
}

// ---------------------------------------------------------------------------
// Output transform cores: A^T M A for (tile, 2 co)
// ---------------------------------------------------------------------------
__device__ __forceinline__ void otrans_math(float2 (&m)[16], float2 (&y)[2][2]) {
    float2 tmp[2][4];
#pragma unroll
    for (int c = 0; c < 4; ++c) {
        tmp[0][c].x = m[c].x + m[4 + c].x + m[8 + c].x;
        tmp[0][c].y = m[c].y + m[4 + c].y + m[8 + c].y;
        tmp[1][c].x = m[4 + c].x - m[8 + c].x - m[12 + c].x;
        tmp[1][c].y = m[4 + c].y - m[8 + c].y - m[12 + c].y;
    }
#pragma unroll
    for (int r = 0; r < 2; ++r) {
        y[r][0].x = tmp[r][0].x + tmp[r][1].x + tmp[r][2].x;
        y[r][0].y = tmp[r][0].y + tmp[r][1].y + tmp[r][2].y;
        y[r][1].x = tmp[r][1].x - tmp[r][2].x - tmp[r][3].x;
        y[r][1].y = tmp[r][1].y - tmp[r][2].y - tmp[r][3].y;
    }
}

// Fusion output transform: fp16 M -> fp16 aT[p][co]. grid (256, 48=j*16+b)
__global__ void k_otransF(const __half* __restrict__ M16,
                          const float* __restrict__ bias,
                          __half* __restrict__ aT) {
    int tile = blockIdx.x;
    int zb = blockIdx.y, j = zb >> 4, b = zb & 15;
    int t = threadIdx.x;
    int ty = tile >> 4, tx = tile & 15;

    const __half2* M2 = (const __half2*)M16;
    size_t jbase = ((size_t)j * 16) * (MPT / 2);
    float2 m[16];
#pragma unroll
    for (int p = 0; p < 16; ++p)
        m[p] = __half22float2(M2[jbase + (size_t)p * (MPT / 2)
                                 + ((size_t)b * 256 + tile) * 256 + t]);
    float2 y[2][2];
    otrans_math(m, y);
    float2 bv = ((const float2*)bias)[t];
    __half2* out = (__half2*)(aT + (size_t)j * TSZ + (size_t)b * N_ * C_);
#pragma unroll
    for (int r = 0; r < 2; ++r) {
        int p0 = (2 * ty + r) * HW + 2 * tx;
        out[(size_t)p0 * 256 + t]       = __floats2half2_rn(y[r][0].x + bv.x, y[r][0].y + bv.y);
        out[(size_t)(p0 + 1) * 256 + t] = __floats2half2_rn(y[r][1].x + bv.x, y[r][1].y + bv.y);
    }
}

// Final output transform: fp32 M -> fp32 out [s][b][co][p]. grid (256, 48=s*16+b)
__global__ void k_otransO(const float* __restrict__ M32,
                          const float* __restrict__ bias,
                          float* __restrict__ Y) {
    int tile = blockIdx.x;
    int zb = blockIdx.y, s = zb >> 4, b = zb & 15;
    int t = threadIdx.x;
    int ty = tile >> 4, tx = tile & 15;

    const float2* M2 = (const float2*)M32;
    size_t jbase = ((size_t)s * 16) * (MPT / 2);
    float2 m[16];
#pragma unroll
    for (int p = 0; p < 16; ++p)
        m[p] = M2[jbase + (size_t)p * (MPT / 2)
                  + ((size_t)b * 256 + tile) * 256 + t];
    float2 y[2][2];
    otrans_math(m, y);
    float2 bv = ((const float2*)bias)[t];
    float* out = Y + (size_t)s * TSZ + (size_t)b * C_ * N_;
    int co0 = 2 * t;
#pragma unroll
    for (int r = 0; r < 2; ++r) {
        int p0 = (2 * ty + r) * HW + 2 * tx;
        out[(size_t)co0 * N_ + p0]           = y[r][0].x + bv.x;
        out[(size_t)co0 * N_ + p0 + 1]       = y[r][1].x + bv.x;
        out[(size_t)(co0 + 1) * N_ + p0]     = y[r][0].y + bv.y;
        out[(size_t)(co0 + 1) * N_ + p0 + 1] = y[r][1].y + bv.y;
    }
}

// ---------------------------------------------------------------------------
// k_gemmRU_all: 3 fused reset+update GEMMs, M=1024 (r|u), 256x128 tiles.
// ---------------------------------------------------------------------------
__global__ void __launch_bounds__(256, 1) k_gemmRU_all(
        const __half* __restrict__ Wru, const __half* __restrict__ aT,
        const __half* __restrict__ exT, const __half* __restrict__ qT,
        const __half* __restrict__ q1T,
        float* __restrict__ hex, float* __restrict__ hq, float* __restrict__ hq1,
        const float* __restrict__ b_r, const float* __restrict__ b_u,
        __half* __restrict__ rhT, float* __restrict__ u) {
    GEMM_PRE();
    int z = blockIdx.z, j = z >> 4, b = z & 15;
    int co0 = blockIdx.y * 256, p0 = blockIdx.x * 128;
    const __half* hTj = sel3(j, exT, qT, q1T);
    const __half* arow = Wru + (size_t)(co0 + t) * (2 * C_);
    const __half* xrow = aT + (size_t)j * TSZ + (size_t)b * N_ * C_ + (size_t)(p0 + (t & 127)) * C_;
    const __half* hrow = hTj + (size_t)b * N_ * C_ + (size_t)(p0 + (t & 127)) * C_;

    auto issue = [&](int it) {
        int ci0 = it * 16;
        uint32_t da = sAs + (it & 3) * ASTG + t * 48;
        const __half* pa = arow + ci0;
        cpa16(da, pa, 16); cpa16(da + 16, pa + 8, 16);
        if (t < 128) {
            uint32_t db = sBs + (it & 3) * BSTG + t * 48;
            const __half* pb = (ci0 < C_) ? (xrow + ci0) : (hrow + ci0 - C_);
            cpa16(db, pb, 16); cpa16(db + 16, pb + 8, 16);
        }
    };

    ZERO_ACC(acc);
    GEMM_PIPE((2 * C_) / 16, issue, acc);

    bool isR = co0 < C_;
    if (isR) {
        const float* hb = sel3cf(j, hex, hq, hq1) + (size_t)b * C_ * N_;
        __half* rh = rhT + (size_t)j * TSZ + (size_t)b * N_ * C_;
#pragma unroll
        for (int mt = 0; mt < 4; ++mt)
#pragma unroll
            for (int nt = 0; nt < 8; ++nt) {
                int row = co0 + wm + mt * 16 + g;
                int col = p0 + wn + nt * 8 + tg * 2;
                float bv0 = b_r[row], bv1 = b_r[row + 8];
                float o0 = sigm(acc[mt][nt][0] + bv0) * hb[(size_t)row * N_ + col];
                float o1 = sigm(acc[mt][nt][1] + bv0) * hb[(size_t)row * N_ + col + 1];
                float o2 = sigm(acc[mt][nt][2] + bv1) * hb[(size_t)(row + 8) * N_ + col];
                float o3 = sigm(acc[mt][nt][3] + bv1) * hb[(size_t)(row + 8) * N_ + col + 1];
                rh[(size_t)col * C_ + row]           = __float2half_rn(o0);
                rh[(size_t)(col + 1) * C_ + row]     = __float2half_rn(o1);
                rh[(size_t)col * C_ + row + 8]       = __float2half_rn(o2);
                rh[(size_t)(col + 1) * C_ + row + 8] = __float2half_rn(o3);
            }
    } else {
        int rbase = co0 - C_;
        float* ub = u + (size_t)j * TSZ + (size_t)b * C_ * N_;
#pragma unroll
        for (int mt = 0; mt < 4; ++mt)
#pragma unroll
            for (int nt = 0; nt < 8; ++nt) {
                int row = rbase + wm + mt * 16 + g;
                int col = p0 + wn + nt * 8 + tg * 2;
                float bv0 = b_u[row], bv1 = b_u[row + 8];
                *(float2*)(ub + (size_t)row * N_ + col) =
                    make_float2(sigm(acc[mt][nt][0] + bv0), sigm(acc[mt][nt][1] + bv0));
                *(float2*)(ub + (size_t)(row + 8) * N_ + col) =
                    make_float2(sigm(acc[mt][nt][2] + bv1), sigm(acc[mt][nt][3] + bv1));
            }
    }
}

// ---------------------------------------------------------------------------
// k_gemmCAND_all: 3 candidate GEMMs, c = tanh(Wc@[x;r*h]+b), 256x128 tiles.
// ---------------------------------------------------------------------------
__global__ void __launch_bounds__(256, 1) k_gemmCAND_all(
        const __half* __restrict__ Wc, const __half* __restrict__ aT,
        const __half* __restrict__ rhT, const float* __restrict__ bias,
        float* __restrict__ cbuf) {
    GEMM_PRE();
    int z = blockIdx.z, j = z >> 4, b = z & 15;
    int co0 = blockIdx.y * 256, p0 = blockIdx.x * 128;
    const __half* arow  = Wc + (size_t)(co0 + t) * (2 * C_);
    const __half* xrow  = aT  + (size_t)j * TSZ + (size_t)b * N_ * C_ + (size_t)(p0 + (t & 127)) * C_;
    const __half* rhrow = rhT + (size_t)j * TSZ + (size_t)b * N_ * C_ + (size_t)(p0 + (t & 127)) * C_;
    float* Yb = cbuf + (size_t)j * TSZ + (size_t)b * C_ * N_;

    auto issue = [&](int it) {
        int ci0 = it * 16;
        uint32_t da = sAs + (it & 3) * ASTG + t * 48;
        const __half* pa = arow + ci0;
        cpa16(da, pa, 16); cpa16(da + 16, pa + 8, 16);
        if (t < 128) {
            uint32_t db = sBs + (it & 3) * BSTG + t * 48;
            const __half* pb = (ci0 < C_) ? (xrow + ci0) : (rhrow + ci0 - C_);
            cpa16(db, pb, 16); cpa16(db + 16, pb + 8, 16);
        }
    };

    ZERO_ACC(acc);
    GEMM_PIPE((2 * C_) / 16, issue, acc);

#pragma unroll
    for (int mt = 0; mt < 4; ++mt)
#pragma unroll
        for (int nt = 0; nt < 8; ++nt) {
            int row = co0 + wm + mt * 16 + g;
            int col = p0 + wn + nt * 8 + tg * 2;
            float bv0 = bias[row], bv1 = bias[row + 8];
            *(float2*)(Yb + (size_t)row * N_ + col) =
                make_float2(tanhf(acc[mt][nt][0] + bv0), tanhf(acc[mt][nt][1] + bv0));
            *(float2*)(Yb + (size_t)(row + 8) * N_ + col) =
                make_float2(tanhf(acc[mt][nt][2] + bv1), tanhf(acc[mt][nt][3] + bv1));
        }
}

// ---------------------------------------------------------------------------
// k_gruout_all: h = h(1-u)+cu for 3 states, emits fp16 mirrors. grid (32,16,48)
// ---------------------------------------------------------------------------
__global__ void k_gruout_all(
        float* __restrict__ hex, float* __restrict__ hq, float* __restrict__ hq1,
        const float* __restrict__ u, const float* __restrict__ c,
        __half* __restrict__ n16_0, __half* __restrict__ n16_1, __half* __restrict__ n16_2,
        __half* __restrict__ nT_0, __half* __restrict__ nT_1, __half* __restrict__ nT_2) {
    __shared__ float tile[32][33];
    int z = blockIdx.z, s = z >> 4, b = z & 15;
    float*       hb = sel3f(s, hex, hq, hq1) + (size_t)b * C_ * N_;
    const float* ub = u + (size_t)s * TSZ + (size_t)b * C_ * N_;
    const float* cb = c + (size_t)s * TSZ + (size_t)b * C_ * N_;
    __half* on = sel3h(s, n16_0, n16_1, n16_2) + (size_t)b * C_ * N_;
    __half* ot = sel3h(s, nT_0, nT_1, nT_2)    + (size_t)b * N_ * C_;
    int n0 = blockIdx.x * 32, c0 = blockIdx.y * 32;
    int tx = threadIdx.x, ty = threadIdx.y;
#pragma unroll
    for (int j = 0; j < 4; ++j) {
        size_t idx = (size_t)(c0 + ty + 8 * j) * N_ + n0 + tx;
        float hv = hb[idx] * (1.f - ub[idx]) + cb[idx] * ub[idx];
        hb[idx] = hv;
        on[idx] = __float2half_rn(hv);
        tile[ty + 8 * j][tx] = hv;
    }
    __syncthreads();
#pragma unroll
    for (int j = 0; j < 4; ++j)
        ot[(size_t)(n0 + ty + 8 * j) * C_ + c0 + tx] = __float2half_rn(tile[tx][ty + 8 * j]);
}

// ---------------------------------------------------------------------------
// Prep kernels
// ---------------------------------------------------------------------------
__global__ void k_prep_g(const float* __restrict__ wr, const float* __restrict__ wu,
                         const float* __restrict__ wc,
                         __half* __restrict__ oru, __half* __restrict__ oc) {
    size_t i = (size_t)blockIdx.x * 256 + threadIdx.x;
    size_t half = (size_t)C_ * 2 * C_;
    if (i < half) oru[i] = __float2half_rn(wr[i]);
    else if (i < 2 * half) oru[i] = __float2half_rn(wu[i - half]);
    else if (i < 3 * half) oc[i - 2 * half] = __float2half_rn(wc[i - 2 * half]);
}

__global__ void k_premirror(
        const float* __restrict__ in1, const float* __restrict__ in2,
        const float* __restrict__ in3,
        float* __restrict__ hex, float* __restrict__ hq, float* __restrict__ hq1,
        __half* __restrict__ m16_0, __half* __restrict__ m16_1, __half* __restrict__ m16_2,
        __half* __restrict__ mT_0, __half* __restrict__ mT_1, __half* __restrict__ mT_2,
        __half* __restrict__ i1T, __half* __restrict__ i2T, __half* __restrict__ i3T) {
    __shared__ float tile[32][33];
    int z = blockIdx.z;
    int tx = threadIdx.x, ty = threadIdx.y;
    int n0 = blockIdx.x * 32, c0 = blockIdx.y * 32;
    if (z < 48) {
        int s = z >> 4, b = z & 15;
        const float* ib = sel3cf(s, in1, in2, in3) + (size_t)b * C_ * N_;
        float* hb = sel3f(s, hex, hq, hq1) + (size_t)b * C_ * N_;
        __half* on = sel3h(s, m16_0, m16_1, m16_2) + (size_t)b * C_ * N_;
        __half* ot = sel3h(s, mT_0, mT_1, mT_2)    + (size_t)b * N_ * C_;
#pragma unroll
        for (int j = 0; j < 4; ++j) {
            size_t idx = (size_t)(c0 + ty + 8 * j) * N_ + n0 + tx;
            float v = ib[idx];
            hb[idx] = v;
            on[idx] = __float2half_rn(v);
            tile[ty + 8 * j][tx] = v;
        }
        __syncthreads();
#pragma unroll
        for (int j = 0; j < 4; ++j)
            ot[(size_t)(n0 + ty + 8 * j) * C_ + c0 + tx] = __float2half_rn(tile[tx][ty + 8 * j]);
    } else {
        int s = (z - 48) >> 4, b = (z - 48) & 15;
        const float* ib = sel3cf(s, in1, in2, in3) + (size_t)b * C_ * N_;
        __half* ot = sel3h(s, i1T, i2T, i3T) + (size_t)b * N_ * C_;
#pragma unroll
        for (int j = 0; j < 4; ++j)
            tile[ty + 8 * j][tx] = ib[(size_t)(c0 + ty + 8 * j) * N_ + n0 + tx];
        __syncthreads();
#pragma unroll
        for (int j = 0; j < 4; ++j)
            ot[(size_t)(n0 + ty + 8 * j) * C_ + c0 + tx] = __float2half_rn(tile[tx][ty + 8 * j]);
    }
}

// ---------------------------------------------------------------------------
// Host orchestration
// ---------------------------------------------------------------------------
extern "C" void kernel_launch(void* const* d_in, const int* in_sizes, int n_in,
                              void* d_out, int out_size) {
    const float* in1      = (const float*)d_in[0];
    const float* in2      = (const float*)d_in[1];
    const float* in3      = (const float*)d_in[2];
    const float* w_fusion = (const float*)d_in[3];
    const float* b_fusion = (const float*)d_in[4];
    const float* w_out    = (const float*)d_in[5];
    const float* b_out    = (const float*)d_in[6];
    const float* w_reset  = (const float*)d_in[7];
    const float* b_reset  = (const float*)d_in[8];
    const float* w_update = (const float*)d_in[9];
    const float* b_update = (const float*)d_in[10];
    const float* w_cand   = (const float*)d_in[11];
    const float* b_cand   = (const float*)d_in[12];
    float* out = (float*)d_out;

    cudaFuncSetAttribute(k_scores_all,   cudaFuncAttributeMaxDynamicSharedMemorySize, SMEM_DYN);
    cudaFuncSetAttribute(k_attmmT_all,   cudaFuncAttributeMaxDynamicSharedMemorySize, SMEM_DYN);
    cudaFuncSetAttribute(k_wino,         cudaFuncAttributeMaxDynamicSharedMemorySize, SMEM_DYN);
    cudaFuncSetAttribute(k_winoF,        cudaFuncAttributeMaxDynamicSharedMemorySize, SMEM_DYN);
    cudaFuncSetAttribute(k_gemmRU_all,   cudaFuncAttributeMaxDynamicSharedMemorySize, SMEM_DYN);
    cudaFuncSetAttribute(k_gemmCAND_all, cudaFuncAttributeMaxDynamicSharedMemorySize, SMEM_DYN);

    float *S, *ex, *q, *q1, *u, *c, *M32;
    __half *M16, *P16, *OT, *aT, *rhT, *in1T, *in2T, *in3T, *V, *Uf, *Uo;
    __half *wru16, *wc16;
    __half *m16a[3], *m16b[3], *mTa[3], *mTb[3];
    cudaGetSymbolAddress((void**)&S,    g_S);
    cudaGetSymbolAddress((void**)&ex,   g_ex);
    cudaGetSymbolAddress((void**)&q,    g_q);
    cudaGetSymbolAddress((void**)&q1,   g_q1);
    cudaGetSymbolAddress((void**)&u,    g_u);
    cudaGetSymbolAddress((void**)&c,    g_c);
    cudaGetSymbolAddress((void**)&M32,  g_M32);
    cudaGetSymbolAddress((void**)&M16,  g_M16);
    cudaGetSymbolAddress((void**)&P16,  g_P16);
    cudaGetSymbolAddress((void**)&OT,   g_OT);
    cudaGetSymbolAddress((void**)&aT,   g_aT);
    cudaGetSymbolAddress((void**)&rhT,  g_rhT);
    cudaGetSymbolAddress((void**)&V,    g_V);
    cudaGetSymbolAddress((void**)&Uf,   g_Uf);
    cudaGetSymbolAddress((void**)&Uo,   g_Uo);
    cudaGetSymbolAddress((void**)&in1T, g_in1T16);
    cudaGetSymbolAddress((void**)&in2T, g_in2T16);
    cudaGetSymbolAddress((void**)&in3T, g_in3T16);
    cudaGetSymbolAddress((void**)&wru16, g_wru16);
    cudaGetSymbolAddress((void**)&wc16, g_wc16);
    cudaGetSymbolAddress((void**)&m16a[0], g_ex16a);
    cudaGetSymbolAddress((void**)&m16a[1], g_q16a);
    cudaGetSymbolAddress((void**)&m16a[2], g_q116a);
    cudaGetSymbolAddress((void**)&m16b[0], g_ex16b);
    cudaGetSymbolAddress((void**)&m16b[1], g_q16b);
    cudaGetSymbolAddress((void**)&m16b[2], g_q116b);
    cudaGetSymbolAddress((void**)&mTa[0], g_exT16a);
    cudaGetSymbolAddress((void**)&mTa[1], g_qT16a);
    cudaGetSymbolAddress((void**)&mTa[2], g_q1T16a);
    cudaGetSymbolAddress((void**)&mTb[0], g_exT16b);
    cudaGetSymbolAddress((void**)&mTb[1], g_qT16b);
    cudaGetSymbolAddress((void**)&mTb[2], g_q1T16b);

    const int GG = (int)((3 * (size_t)C_ * 2 * C_ + 255) / 256);

    // prep (4 launches)
    k_prep_g<<<GG, 256>>>(w_reset, w_update, w_cand, wru16, wc16);
    k_wt_wino<<<2048, 256>>>(w_fusion, Uf);
    k_wt_wino<<<2048, 256>>>(w_out, Uo);
    k_premirror<<<dim3(32, 16, 96), dim3(32, 8)>>>(
        in1, in2, in3, ex, q, q1,
        m16a[0], m16a[1], m16a[2], mTa[0], mTa[1], mTa[2],
        in1T, in2T, in3T);

    __half** cur16 = m16a;  __half** curT = mTa;
    __half** nw16  = m16b;  __half** nwT  = mTb;

    for (int round = 0; round < 5; ++round) {
        k_scores_all<<<dim3(8, 4, 96), 256, SMEM_DYN>>>(curT[0], curT[1], curT[2], S);
        k_softmax_all<<<6 * B_ * N_, 256>>>(S, P16);
        k_attmmT_all<<<dim3(4, 4, 96), 256, SMEM_DYN>>>(P16, cur16[0], cur16[1], cur16[2], OT);

        // fusion convs via Winograd F(2x2,3x3), fp16 M
        k_dtransF<<<dim3(256, 48), 256>>>(OT, V);
        k_winoF<<<dim3(4, 1, 768), 256, SMEM_DYN>>>(V, Uf, M16);
        k_otransF<<<dim3(256, 48), 256>>>(M16, b_fusion, aT);

        k_gemmRU_all<<<dim3(8, 4, 48), 256, SMEM_DYN>>>(
            wru16, aT, curT[0], curT[1], curT[2], ex, q, q1,
            b_reset, b_update, rhT, u);
        k_gemmCAND_all<<<dim3(8, 2, 48), 256, SMEM_DYN>>>(wc16, aT, rhT, b_cand, c);
        k_gruout_all<<<dim3(32, 16, 48), dim3(32, 8)>>>(
            ex, q, q1, u, c,
            nw16[0], nw16[1], nw16[2], nwT[0], nwT[1], nwT[2]);

        __half** t16 = cur16; cur16 = nw16; nw16 = t16;
        __half** tT  = curT;  curT  = nwT;  nwT  = tT;
    }

    // final output convs via Winograd (fp32 M — output-precision path untouched)
    k_dtransO<<<dim3(256, 48), 256>>>(curT[0], curT[1], curT[2],
                                      in1T, in2T, in3T, V);
    k_wino<<<dim3(4, 1, 768), 256, SMEM_DYN>>>(V, Uo, M32);
    k_otransO<<<dim3(256, 48), 256>>>(M32, b_out, out);
}

// round 17
// speedup vs baseline: 1.1500x; 1.1273x over previous
#include <cuda_runtime.h>
#include <cuda_fp16.h>
#include <math.h>
#include <stdint.h>

// ---------------------------------------------------------------------------
// Problem constants
// ---------------------------------------------------------------------------
#define B_  16
#define C_  512
#define N_  1024
#define HW  32
#define SPITCH 12                      // smem row stride in u32 (48B) - conflict-free
#define NSTG 4                         // pipeline stages
#define ASTG (256 * SPITCH * 4)        // 12288 B per A stage (256 rows)
#define BSTG (128 * SPITCH * 4)        // 6144 B per B stage (128 rows)
#define SMEM_DYN (NSTG * (ASTG + BSTG))   // 73728 B

static constexpr size_t TSZ  = (size_t)B_ * C_ * N_;
static constexpr size_t SSZ  = (size_t)B_ * N_ * N_;
static constexpr size_t VPT  = (size_t)16 * 256 * 1024;   // F(2,3) V halfs per (s,point)
static constexpr size_t MPT  = (size_t)16 * 256 * 512;    // F(2,3) M elems per (s,point)
static constexpr size_t VPT4 = (size_t)1024 * 1024;       // F(4,3) V halfs per (j,point) (b*64+tile rows)
static constexpr size_t MPT4 = (size_t)1024 * 512;        // F(4,3) M halfs per (j,point)

// ---------------------------------------------------------------------------
// Scratch (static device globals; no allocation anywhere)
// ---------------------------------------------------------------------------
__device__ float g_S [6 * SSZ];
__device__ float g_ex[TSZ], g_q [TSZ], g_q1[TSZ];
__device__ float g_u [3 * TSZ], g_c [3 * TSZ];
__device__ float g_M32[(size_t)3 * 16 * MPT];      // fp32 M (final conv path, F(2,3))

__device__ __align__(128) __half g_M164[(size_t)3 * 36 * MPT4];  // fp16 M (fusion F(4,3))
__device__ __align__(128) __half g_V4 [(size_t)3 * 36 * VPT4];   // F(4,3) data
__device__ __align__(128) __half g_U4 [(size_t)36 * C_ * (2 * C_)]; // F(4,3) weights
__device__ __align__(128) __half g_P16[6 * SSZ];
__device__ __align__(128) __half g_OT [6 * TSZ];   // attention outputs [p][c]
__device__ __align__(128) __half g_aT [3 * TSZ];   // fusion outputs [p][c]
__device__ __align__(128) __half g_rhT[3 * TSZ];
__device__ __align__(128) __half g_V  [(size_t)3 * 16 * VPT];   // F(2,3) data (final path)
__device__ __align__(128) __half g_Uo [(size_t)16 * C_ * (2 * C_)]; // F(2,3) wo
__device__ __align__(128) __half g_ex16a [TSZ], g_q16a [TSZ], g_q116a[TSZ];
__device__ __align__(128) __half g_ex16b [TSZ], g_q16b [TSZ], g_q116b[TSZ];
__device__ __align__(128) __half g_exT16a[TSZ], g_qT16a[TSZ], g_q1T16a[TSZ];
__device__ __align__(128) __half g_exT16b[TSZ], g_qT16b[TSZ], g_q1T16b[TSZ];
__device__ __align__(128) __half g_in1T16[TSZ], g_in2T16[TSZ], g_in3T16[TSZ];
__device__ __align__(128) __half g_wru16[(size_t)(2 * C_) * (2 * C_)];
__device__ __align__(128) __half g_wc16 [(size_t)C_ * (2 * C_)];

// ---------------------------------------------------------------------------
// Helpers
// ---------------------------------------------------------------------------
__device__ __forceinline__ const __half* sel3(int i, const __half* a,
                                              const __half* b, const __half* c) {
    return i == 0 ? a : (i == 1 ? b : c);
}
__device__ __forceinline__ __half* sel3h(int i, __half* a, __half* b, __half* c) {
    return i == 0 ? a : (i == 1 ? b : c);
}
__device__ __forceinline__ float* sel3f(int i, float* a, float* b, float* c) {
    return i == 0 ? a : (i == 1 ? b : c);
}
__device__ __forceinline__ const float* sel3cf(int i, const float* a,
                                               const float* b, const float* c) {
    return i == 0 ? a : (i == 1 ? b : c);
}
__device__ __forceinline__ int pairB(int j) {
    switch (j) { case 0: return 1; case 1: return 2; case 2: return 0;
                 case 3: return 2; case 4: return 0; default: return 1; }
}
__device__ __forceinline__ float sigm(float x) { return 1.f / (1.f + __expf(-x)); }

__device__ __forceinline__ void cpa16(uint32_t dst, const void* src, uint32_t sz) {
    asm volatile("cp.async.ca.shared.global [%0], [%1], 16, %2;"
                 :: "r"(dst), "l"(src), "r"(sz) : "memory");
}
#define CP_COMMIT() asm volatile("cp.async.commit_group;" ::: "memory")
#define CP_WAIT2()  asm volatile("cp.async.wait_group 2;" ::: "memory")

// float2 arithmetic helpers
__device__ __forceinline__ float2 f2add(float2 a, float2 b) { return make_float2(a.x + b.x, a.y + b.y); }
__device__ __forceinline__ float2 f2sub(float2 a, float2 b) { return make_float2(a.x - b.x, a.y - b.y); }
__device__ __forceinline__ float2 f2scl(float s, float2 a)  { return make_float2(s * a.x, s * a.y); }

// ---------------------------------------------------------------------------
// fp16 mma.sync microkernel. Block tile 256x128, 8 warps (4m x 2n of 64x64).
// ---------------------------------------------------------------------------
__device__ __forceinline__ void mma16(float* d, const uint32_t* a, uint32_t b0, uint32_t b1) {
    asm volatile(
        "mma.sync.aligned.m16n8k16.row.col.f32.f16.f16.f32 "
        "{%0,%1,%2,%3}, {%4,%5,%6,%7}, {%8,%9}, {%0,%1,%2,%3};\n"
        : "+f"(d[0]), "+f"(d[1]), "+f"(d[2]), "+f"(d[3])
        : "r"(a[0]), "r"(a[1]), "r"(a[2]), "r"(a[3]), "r"(b0), "r"(b1));
}

__device__ __forceinline__ void ldsm4(uint32_t* r, uint32_t addr) {
    asm volatile(
        "ldmatrix.sync.aligned.m8n8.x4.shared.b16 {%0,%1,%2,%3}, [%4];"
        : "=r"(r[0]), "=r"(r[1]), "=r"(r[2]), "=r"(r[3]) : "r"(addr));
}

__device__ __forceinline__ void compute16(uint32_t aB, uint32_t bB,
                                          float (*acc)[8][4], int wm, int wn,
                                          int lane) {
    int lr = lane & 15;
    uint32_t lc = (uint32_t)(lane >> 4) * 16;
    uint32_t a[4][4], b[4][4];
#pragma unroll
    for (int mt = 0; mt < 4; ++mt)
        ldsm4(a[mt], aB + (uint32_t)(wm + mt * 16 + lr) * (SPITCH * 4) + lc);
#pragma unroll
    for (int np = 0; np < 4; ++np)
        ldsm4(b[np], bB + (uint32_t)(wn + np * 16 + lr) * (SPITCH * 4) + lc);
#pragma unroll
    for (int mt = 0; mt < 4; ++mt)
#pragma unroll
        for (int np = 0; np < 4; ++np) {
            mma16(acc[mt][2 * np],     a[mt], b[np][0], b[np][2]);
            mma16(acc[mt][2 * np + 1], a[mt], b[np][1], b[np][3]);
        }
}

#define ZERO_ACC(acc)                                       \
    float acc[4][8][4];                                     \
    _Pragma("unroll")                                       \
    for (int i_ = 0; i_ < 4; ++i_)                          \
        _Pragma("unroll")                                   \
        for (int j_ = 0; j_ < 8; ++j_)                      \
            _Pragma("unroll")                               \
            for (int v_ = 0; v_ < 4; ++v_) acc[i_][j_][v_] = 0.f;

#define GEMM_PRE()                                                           \
    extern __shared__ __align__(1024) char dsm[];                            \
    int t = threadIdx.x, lane = t & 31, wid = t >> 5;                        \
    int wm = (wid & 3) * 64, wn = (wid >> 2) * 64;                           \
    int g = lane >> 2, tg = lane & 3;                                        \
    uint32_t sAs = (uint32_t)__cvta_generic_to_shared(dsm);                  \
    uint32_t sBs = sAs + NSTG * ASTG;                                        \
    (void)g; (void)tg;

#define GEMM_PIPE(KI, ISSUE, acc)                                            \
    for (int s_ = 0; s_ < 3; ++s_) { ISSUE(s_); CP_COMMIT(); }               \
    for (int it_ = 0; it_ < (KI); ++it_) {                                   \
        CP_WAIT2();                                                          \
        __syncthreads();                                                     \
        compute16(sAs + (it_ & 3) * ASTG, sBs + (it_ & 3) * BSTG,            \
                  acc, wm, wn, lane);                                        \
        if (it_ + 3 < (KI)) ISSUE(it_ + 3);                                  \
        CP_COMMIT();                                                         \
    }

// ---------------------------------------------------------------------------
// k_scores_all: 6 logits GEMMs, 256x128 tiles. grid (8,4,96), 256 thr
// ---------------------------------------------------------------------------
__global__ void __launch_bounds__(256, 1) k_scores_all(
        const __half* __restrict__ exT, const __half* __restrict__ qT,
        const __half* __restrict__ q1T, float* __restrict__ S) {
    GEMM_PRE();
    int z = blockIdx.z, j = z >> 4, b = z & 15;
    const __half* A  = sel3(j >> 1,   exT, qT, q1T);
    const __half* Bm = sel3(pairB(j), exT, qT, q1T);
    int n0 = blockIdx.y * 256, m0 = blockIdx.x * 128;
    const __half* arow = A  + (size_t)b * N_ * C_ + (size_t)(n0 + t) * C_;
    const __half* brow = Bm + (size_t)b * N_ * C_ + (size_t)(m0 + (t & 127)) * C_;
    float* Sb = S + (size_t)j * SSZ + (size_t)b * N_ * N_;

    auto issue = [&](int it) {
        uint32_t da = sAs + (it & 3) * ASTG + t * 48;
        const __half* pa = arow + it * 16;
        cpa16(da, pa, 16); cpa16(da + 16, pa + 8, 16);
        if (t < 128) {
            uint32_t db = sBs + (it & 3) * BSTG + t * 48;
            const __half* pb = brow + it * 16;
            cpa16(db, pb, 16); cpa16(db + 16, pb + 8, 16);
        }
    };

    ZERO_ACC(acc);
    GEMM_PIPE(C_ / 16, issue, acc);

#pragma unroll
    for (int mt = 0; mt < 4; ++mt)
#pragma unroll
        for (int nt = 0; nt < 8; ++nt) {
            int row = n0 + wm + mt * 16 + g;
            int col = m0 + wn + nt * 8 + tg * 2;
            *(float2*)(Sb + (size_t)row * N_ + col)       = make_float2(acc[mt][nt][0], acc[mt][nt][1]);
            *(float2*)(Sb + (size_t)(row + 8) * N_ + col) = make_float2(acc[mt][nt][2], acc[mt][nt][3]);
        }
}

// ---------------------------------------------------------------------------
// Row softmax over all 6 matrices. grid 6*B_*N_, 256 thr
// ---------------------------------------------------------------------------
__global__ void __launch_bounds__(256) k_softmax_all(const float* __restrict__ S,
                                                     __half* __restrict__ P) {
    const float* row = S + (size_t)blockIdx.x * N_;
    __half*      out = P + (size_t)blockIdx.x * N_;
    int t = threadIdx.x;
    float4 v = *(const float4*)(row + 4 * t);
    __shared__ float red[8];

    float m = fmaxf(fmaxf(v.x, v.y), fmaxf(v.z, v.w));
#pragma unroll
    for (int o = 16; o; o >>= 1) m = fmaxf(m, __shfl_xor_sync(0xffffffffu, m, o));
    if ((t & 31) == 0) red[t >> 5] = m;
    __syncthreads();
    float mx = red[0];
#pragma unroll
    for (int i = 1; i < 8; ++i) mx = fmaxf(mx, red[i]);
    __syncthreads();

    v.x = __expf(v.x - mx); v.y = __expf(v.y - mx);
    v.z = __expf(v.z - mx); v.w = __expf(v.w - mx);
    float s = v.x + v.y + v.z + v.w;
#pragma unroll
    for (int o = 16; o; o >>= 1) s += __shfl_xor_sync(0xffffffffu, s, o);
    if ((t & 31) == 0) red[t >> 5] = s;
    __syncthreads();
    float tot = red[0];
#pragma unroll
    for (int i = 1; i < 8; ++i) tot += red[i];
    float inv = 1.f / tot;

    *(__half2*)(out + 4 * t)     = __floats2half2_rn(v.x * inv, v.y * inv);
    *(__half2*)(out + 4 * t + 2) = __floats2half2_rn(v.z * inv, v.w * inv);
}

// ---------------------------------------------------------------------------
// k_attmmT_all: 6 attention-output GEMMs, fp16 [p][c], 256x128 tiles.
// ---------------------------------------------------------------------------
__global__ void __launch_bounds__(256, 1) k_attmmT_all(
        const __half* __restrict__ P,
        const __half* __restrict__ ex16, const __half* __restrict__ q16,
        const __half* __restrict__ q116, __half* __restrict__ OT) {
    GEMM_PRE();
    int z = blockIdx.z, j = z >> 4, b = z & 15;
    const __half* Bn = sel3(pairB(j), ex16, q16, q116);
    int n0 = blockIdx.y * 256, c0 = blockIdx.x * 128;
    const __half* arow = P  + (size_t)j * SSZ + (size_t)b * N_ * N_ + (size_t)(n0 + t) * N_;
    const __half* brow = Bn + (size_t)b * C_ * N_ + (size_t)(c0 + (t & 127)) * N_;
    __half* Ob = OT + (size_t)j * TSZ + (size_t)b * N_ * C_;

    auto issue = [&](int it) {
        uint32_t da = sAs + (it & 3) * ASTG + t * 48;
        const __half* pa = arow + it * 16;
        cpa16(da, pa, 16); cpa16(da + 16, pa + 8, 16);
        if (t < 128) {
            uint32_t db = sBs + (it & 3) * BSTG + t * 48;
            const __half* pb = brow + it * 16;
            cpa16(db, pb, 16); cpa16(db + 16, pb + 8, 16);
        }
    };

    ZERO_ACC(acc);
    GEMM_PIPE(N_ / 16, issue, acc);

#pragma unroll
    for (int mt = 0; mt < 4; ++mt)
#pragma unroll
        for (int nt = 0; nt < 8; ++nt) {
            int row = n0 + wm + mt * 16 + g;
            int col = c0 + wn + nt * 8 + tg * 2;
            *(__half2*)(Ob + (size_t)row * C_ + col) =
                __floats2half2_rn(acc[mt][nt][0], acc[mt][nt][1]);
            *(__half2*)(Ob + (size_t)(row + 8) * C_ + col) =
                __floats2half2_rn(acc[mt][nt][2], acc[mt][nt][3]);
        }
}

// ---------------------------------------------------------------------------
// F(4,3) data transform: B^T d B (6x6) on fusion-conv inputs (OT pair).
// grid (64 tiles, 48 = j*16+b), 256 thr (one half2 ci column per source half)
// V4 layout: [j*36+p][b*64+tile][ci] fp16
// ---------------------------------------------------------------------------
__global__ void k_dtransF4(const __half* __restrict__ OT, __half* __restrict__ V4) {
    int tile = blockIdx.x;               // 0..63 -> 8x8 grid of 4x4 tiles
    int zb = blockIdx.y, j = zb >> 4, b = zb & 15;
    int t = threadIdx.x;
    int ty = tile >> 3, tx = tile & 7;

    const __half2* x0 = (const __half2*)(OT + (size_t)(2 * j)     * TSZ + (size_t)b * N_ * C_);
    const __half2* x1 = (const __half2*)(OT + (size_t)(2 * j + 1) * TSZ + (size_t)b * N_ * C_);
    __half2* V2 = (__half2*)V4;
    size_t base = (size_t)(j * 36) * (VPT4 / 2);
    size_t rowoff = ((size_t)b * 64 + tile) * 512;

#pragma unroll
    for (int cc = 0; cc < 2; ++cc) {
        const __half2* src = cc ? x1 : x0;
        int ci2 = t + 256 * cc;
        float2 d[6][6];
#pragma unroll
        for (int r = 0; r < 6; ++r) {
            int iy = 4 * ty - 1 + r;
#pragma unroll
            for (int s = 0; s < 6; ++s) {
                int ix = 4 * tx - 1 + s;
                float2 v = make_float2(0.f, 0.f);
                if ((unsigned)iy < HW && (unsigned)ix < HW)
                    v = __half22float2(src[(size_t)(iy * HW + ix) * 256 + t]);
                d[r][s] = v;
            }
        }
        // column transform (B^T applied to each column), in place
#pragma unroll
        for (int s = 0; s < 6; ++s) {
            float2 x0v = d[0][s], x1v = d[1][s], x2v = d[2][s];
            float2 x3v = d[3][s], x4v = d[4][s], x5v = d[5][s];
            d[0][s] = f2add(f2sub(f2scl(4.f, x0v), f2scl(5.f, x2v)), x4v);
            d[1][s] = f2add(f2add(f2scl(-4.f, f2add(x1v, x2v)), x3v), x4v);
            d[2][s] = f2add(f2sub(f2scl(4.f, f2sub(x1v, x2v)), x3v), x4v);
            d[3][s] = f2add(f2sub(f2scl(2.f, f2sub(x3v, x1v)), x2v), x4v);
            d[4][s] = f2add(f2sub(f2scl(2.f, f2sub(x1v, x3v)), x2v), x4v);
            d[5][s] = f2add(f2sub(f2scl(4.f, x1v), f2scl(5.f, x3v)), x5v);
        }
        // row transform + write
#pragma unroll
        for (int r = 0; r < 6; ++r) {
            float2 x0v = d[r][0], x1v = d[r][1], x2v = d[r][2];
            float2 x3v = d[r][3], x4v = d[r][4], x5v = d[r][5];
            float2 v[6];
            v[0] = f2add(f2sub(f2scl(4.f, x0v), f2scl(5.f, x2v)), x4v);
            v[1] = f2add(f2add(f2scl(-4.f, f2add(x1v, x2v)), x3v), x4v);
            v[2] = f2add(f2sub(f2scl(4.f, f2sub(x1v, x2v)), x3v), x4v);
            v[3] = f2add(f2sub(f2scl(2.f, f2sub(x3v, x1v)), x2v), x4v);
            v[4] = f2add(f2sub(f2scl(2.f, f2sub(x1v, x3v)), x2v), x4v);
            v[5] = f2add(f2sub(f2scl(4.f, x1v), f2scl(5.f, x3v)), x5v);
#pragma unroll
            for (int c = 0; c < 6; ++c) {
                int p = r * 6 + c;
                V2[base + (size_t)p * (VPT4 / 2) + rowoff + ci2] =
                    __floats2half2_rn(v[c].x, v[c].y);
            }
        }
    }
}

// ---------------------------------------------------------------------------
// F(4,3) weight transform: U4_p[co][ci] = (G g G^T)_p from fp32 w_fusion.
// grid 2048, 256 thr: i -> (co = i>>10, ci = i&1023)
// ---------------------------------------------------------------------------
__global__ void k_wt_wino4(const float* __restrict__ w, __half* __restrict__ U4) {
    size_t i = (size_t)blockIdx.x * 256 + threadIdx.x;
    int ci = (int)(i & 1023), co = (int)(i >> 10);
    const float* ws = w + ((size_t)co * (2 * C_) + ci) * 9;
    float gm[3][3];
#pragma unroll
    for (int r = 0; r < 3; ++r)
#pragma unroll
        for (int s = 0; s < 3; ++s) gm[r][s] = ws[r * 3 + s];

    const float i6 = 1.f / 6.f, i12 = 1.f / 12.f, i24 = 1.f / 24.f;
    float Gg[6][3];
#pragma unroll
    for (int s = 0; s < 3; ++s) {
        float a = gm[0][s], bb = gm[1][s], c = gm[2][s];
        Gg[0][s] = 0.25f * a;
        Gg[1][s] = -i6 * (a + bb + c);
        Gg[2][s] = i6 * (-a + bb - c);
        Gg[3][s] = i24 * a + i12 * bb + i6 * c;
        Gg[4][s] = i24 * a - i12 * bb + i6 * c;
        Gg[5][s] = c;
    }
#pragma unroll
    for (int r = 0; r < 6; ++r) {
        float a = Gg[r][0], bb = Gg[r][1], c = Gg[r][2];
        float u[6];
        u[0] = 0.25f * a;
        u[1] = -i6 * (a + bb + c);
        u[2] = i6 * (-a + bb - c);
        u[3] = i24 * a + i12 * bb + i6 * c;
        u[4] = i24 * a - i12 * bb + i6 * c;
        u[5] = c;
#pragma unroll
        for (int s = 0; s < 6; ++s) {
            int p = r * 6 + s;
            U4[((size_t)p * C_ + co) * (2 * C_) + ci] = __float2half_rn(u[s]);
        }
    }
}

// ---------------------------------------------------------------------------
// F(4,3) Winograd GEMM: M_p[r][co] = V4_p[r,:] @ U4_p[co,:]^T, r = b*64+tile.
// M=1024, N=512, K=1024. grid (4,4,108): z = j*36 + p. fp16 M output.
// ---------------------------------------------------------------------------
__global__ void __launch_bounds__(256, 1) k_winoF4(const __half* __restrict__ V4,
                                                   const __half* __restrict__ U4,
                                                   __half* __restrict__ M164) {
    GEMM_PRE();
    int z = blockIdx.z, j = z / 36, p = z % 36;
    int rb0 = blockIdx.y * 256, cb0 = blockIdx.x * 128;
    const __half* arow = V4 + (size_t)(j * 36 + p) * VPT4 + (size_t)(rb0 + t) * 1024;
    const __half* brow = U4 + ((size_t)p * C_ + cb0 + (t & 127)) * (2 * C_);
    __half* Mb = M164 + (size_t)(j * 36 + p) * MPT4;

    auto issue = [&](int it) {
        uint32_t da = sAs + (it & 3) * ASTG + t * 48;
        const __half* pa = arow + it * 16;
        cpa16(da, pa, 16); cpa16(da + 16, pa + 8, 16);
        if (t < 128) {
            uint32_t db = sBs + (it & 3) * BSTG + t * 48;
            const __half* pb = brow + it * 16;
            cpa16(db, pb, 16); cpa16(db + 16, pb + 8, 16);
        }
    };

    ZERO_ACC(acc);
    GEMM_PIPE((2 * C_) / 16, issue, acc);

#pragma unroll
    for (int mt = 0; mt < 4; ++mt)
#pragma unroll
        for (int nt = 0; nt < 8; ++nt) {
            int row = rb0 + wm + mt * 16 + g;
            int col = cb0 + wn + nt * 8 + tg * 2;
            *(__half2*)(Mb + (size_t)row * 512 + col) =
                __floats2half2_rn(acc[mt][nt][0], acc[mt][nt][1]);
            *(__half2*)(Mb + (size_t)(row + 8) * 512 + col) =
                __floats2half2_rn(acc[mt][nt][2], acc[mt][nt][3]);
        }
}

// ---------------------------------------------------------------------------
// F(4,3) output transform: aT[pixel][co] = A^T M A + bias.
// grid (64, 48=j*16+b), 256 thr (2 co per thread via float2).
// ---------------------------------------------------------------------------
__global__ void k_otransF4(const __half* __restrict__ M164,
                           const float* __restrict__ bias,
                           __half* __restrict__ aT) {
    int tile = blockIdx.x;
    int zb = blockIdx.y, j = zb >> 4, b = zb & 15;
    int t = threadIdx.x;
    int ty = tile >> 3, tx = tile & 7;

    const __half2* M2 = (const __half2*)M164;
    size_t rowoff = ((size_t)b * 64 + tile) * 256;
    float2 m[36];
#pragma unroll
    for (int p = 0; p < 36; ++p)
        m[p] = __half22float2(M2[(size_t)(j * 36 + p) * (MPT4 / 2) + rowoff + t]);

    // column transform: z[4][6] = A^T * M (per column)
    float2 zz[4][6];
#pragma unroll
    for (int s = 0; s < 6; ++s) {
        float2 m0 = m[s], m1 = m[6 + s], m2 = m[12 + s];
        float2 m3 = m[18 + s], m4 = m[24 + s], m5 = m[30 + s];
        zz[0][s] = f2add(f2add(f2add(m0, m1), f2add(m2, m3)), m4);
        zz[1][s] = f2add(f2sub(m1, m2), f2scl(2.f, f2sub(m3, m4)));
        zz[2][s] = f2add(f2add(m1, m2), f2scl(4.f, f2add(m3, m4)));
        zz[3][s] = f2add(f2add(f2sub(m1, m2), f2scl(8.f, f2sub(m3, m4))), m5);
    }
    float2 bv = ((const float2*)bias)[t];
    __half2* out = (__half2*)(aT + (size_t)j * TSZ + (size_t)b * N_ * C_);

#pragma unroll
    for (int r = 0; r < 4; ++r) {
        float2 z0 = zz[r][0], z1 = zz[r][1], z2 = zz[r][2];
        float2 z3 = zz[r][3], z4 = zz[r][4], z5 = zz[r][5];
        float2 y[4];
        y[0] = f2add(f2add(f2add(z0, z1), f2add(z2, z3)), z4);
        y[1] = f2add(f2sub(z1, z2), f2scl(2.f, f2sub(z3, z4)));
        y[2] = f2add(f2add(z1, z2), f2scl(4.f, f2add(z3, z4)));
        y[3] = f2add(f2add(f2sub(z1, z2), f2scl(8.f, f2sub(z3, z4))), z5);
        int py = 4 * ty + r;
#pragma unroll
        for (int c = 0; c < 4; ++c) {
            int px = 4 * tx + c;
            out[(size_t)(py * HW + px) * 256 + t] =
                __floats2half2_rn(y[c].x + bv.x, y[c].y + bv.y);
        }
    }
}

// ---------------------------------------------------------------------------
// F(2,3) path (final conv, fp32 M — output-precision path, unchanged)
// ---------------------------------------------------------------------------
__device__ __forceinline__ void dtrans_core(const __half2* x0, const __half2* x1,
                                            __half2* V2, size_t base,
                                            int tile, int b, int t) {
    int ty = tile >> 4, tx = tile & 15;
#pragma unroll
    for (int cc = 0; cc < 2; ++cc) {
        const __half2* src = cc ? x1 : x0;
        int ci2 = t + 256 * cc;
        float lo[4][4], hi[4][4];
#pragma unroll
        for (int r = 0; r < 4; ++r) {
            int iy = 2 * ty - 1 + r;
#pragma unroll
            for (int s = 0; s < 4; ++s) {
                int ix = 2 * tx - 1 + s;
                float2 v = make_float2(0.f, 0.f);
                if ((unsigned)iy < HW && (unsigned)ix < HW)
                    v = __half22float2(src[(size_t)(iy * HW + ix) * 256 + t]);
                lo[r][s] = v.x; hi[r][s] = v.y;
            }
        }
        float tl[4][4], th[4][4];
#pragma unroll
        for (int s = 0; s < 4; ++s) {
            tl[0][s] = lo[0][s] - lo[2][s];  th[0][s] = hi[0][s] - hi[2][s];
            tl[1][s] = lo[1][s] + lo[2][s];  th[1][s] = hi[1][s] + hi[2][s];
            tl[2][s] = lo[2][s] - lo[1][s];  th[2][s] = hi[2][s] - hi[1][s];
            tl[3][s] = lo[1][s] - lo[3][s];  th[3][s] = hi[1][s] - hi[3][s];
        }
#pragma unroll
        for (int r = 0; r < 4; ++r) {
            float vl[4], vh[4];
            vl[0] = tl[r][0] - tl[r][2];  vh[0] = th[r][0] - th[r][2];
            vl[1] = tl[r][1] + tl[r][2];  vh[1] = th[r][1] + th[r][2];
            vl[2] = tl[r][2] - tl[r][1];  vh[2] = th[r][2] - th[r][1];
            vl[3] = tl[r][1] - tl[r][3];  vh[3] = th[r][1] - th[r][3];
#pragma unroll
            for (int c = 0; c < 4; ++c) {
                int p = r * 4 + c;
                V2[base + (size_t)p * (VPT / 2)
                   + ((size_t)b * 256 + tile) * 512 + ci2] = __floats2half2_rn(vl[c], vh[c]);
            }
        }
    }
}

// Final-conv data transform: sources = [stateT ; inT]. grid (256, 48=s*16+b)
__global__ void k_dtransO(const __half* __restrict__ exT, const __half* __restrict__ qT,
                          const __half* __restrict__ q1T,
                          const __half* __restrict__ i1T, const __half* __restrict__ i2T,
                          const __half* __restrict__ i3T, __half* __restrict__ V) {
    int tile = blockIdx.x;
    int zb = blockIdx.y, s = zb >> 4, b = zb & 15;
    const __half2* x0 = (const __half2*)(sel3(s, exT, qT, q1T)   + (size_t)b * N_ * C_);
    const __half2* x1 = (const __half2*)(sel3(s, i1T, i2T, i3T) + (size_t)b * N_ * C_);
    dtrans_core(x0, x1, (__half2*)V, ((size_t)s * 16) * (VPT / 2), tile, b, threadIdx.x);
}

// F(2,3) weight transform (final conv): grid 2048, 256 thr
__global__ void k_wt_wino(const float* __restrict__ w, __half* __restrict__ U) {
    size_t i = (size_t)blockIdx.x * 256 + threadIdx.x;
    int ci = (int)(i & 1023), co = (int)(i >> 10);
    const float* ws = w + ((size_t)co * (2 * C_) + ci) * 9;
    float gm[3][3];
#pragma unroll
    for (int r = 0; r < 3; ++r)
#pragma unroll
        for (int s = 0; s < 3; ++s) gm[r][s] = ws[r * 3 + s];

    float Gg[4][3];
#pragma unroll
    for (int s = 0; s < 3; ++s) {
        Gg[0][s] = gm[0][s];
        Gg[1][s] = 0.5f * (gm[0][s] + gm[1][s] + gm[2][s]);
        Gg[2][s] = 0.5f * (gm[0][s] - gm[1][s] + gm[2][s]);
        Gg[3][s] = gm[2][s];
    }
#pragma unroll
    for (int r = 0; r < 4; ++r) {
        float a = Gg[r][0], bb = Gg[r][1], c = Gg[r][2];
        float u[4] = {a, 0.5f * (a + bb + c), 0.5f * (a - bb + c), c};
#pragma unroll
        for (int s = 0; s < 4; ++s) {
            int p = r * 4 + s;
            U[((size_t)p * C_ + co) * (2 * C_) + ci] = __float2half_rn(u[s]);
        }
    }
}

// F(2,3) Winograd GEMM (fp32 M, final path). grid (4,1,768)
__global__ void __launch_bounds__(256, 1) k_wino(const __half* __restrict__ V,
                                                 const __half* __restrict__ U,
                                                 float* __restrict__ M32) {
    GEMM_PRE();
    int z = blockIdx.z, j = z >> 8, p = (z >> 4) & 15, b = z & 15;
    int cb0 = blockIdx.x * 128;
    const __half* arow = V + ((size_t)(j * 16 + p)) * VPT
                           + ((size_t)b * 256 + t) * 1024;
    const __half* brow = U + ((size_t)p * C_ + cb0 + (t & 127)) * (2 * C_);
    float* Mb = M32 + ((size_t)(j * 16 + p)) * MPT + (size_t)b * 256 * 512;

    auto issue = [&](int it) {
        uint32_t da = sAs + (it & 3) * ASTG + t * 48;
        const __half* pa = arow + it * 16;
        cpa16(da, pa, 16); cpa16(da + 16, pa + 8, 16);
        if (t < 128) {
            uint32_t db = sBs + (it & 3) * BSTG + t * 48;
            const __half* pb = brow + it * 16;
            cpa16(db, pb, 16); cpa16(db + 16, pb + 8, 16);
        }
    };

    ZERO_ACC(acc);
    GEMM_PIPE((2 * C_) / 16, issue, acc);

#pragma unroll
    for (int mt = 0; mt < 4; ++mt)
#pragma unroll
        for (int nt = 0; nt < 8; ++nt) {
            int row = wm + mt * 16 + g;
            int col = cb0 + wn + nt * 8 + tg * 2;
            *(float2*)(Mb + (size_t)row * 512 + col)       = make_float2(acc[mt][nt][0], acc[mt][nt][1]);
            *(float2*)(Mb + (size_t)(row + 8) * 512 + col) = make_float2(acc[mt][nt][2], acc[mt][nt][3]);
        }
}

// F(2,3) output transform math
__device__ __forceinline__ void otrans_math(float2 (&m)[16], float2 (&y)[2][2]) {
    float2 tmp[2][4];
#pragma unroll
    for (int c = 0; c < 4; ++c) {
        tmp[0][c].x = m[c].x + m[4 + c].x + m[8 + c].x;
        tmp[0][c].y = m[c].y + m[4 + c].y + m[8 + c].y;
        tmp[1][c].x = m[4 + c].x - m[8 + c].x - m[12 + c].x;
        tmp[1][c].y = m[4 + c].y - m[8 + c].y - m[12 + c].y;
    }
#pragma unroll
    for (int r = 0; r < 2; ++r) {
        y[r][0].x = tmp[r][0].x + tmp[r][1].x + tmp[r][2].x;
        y[r][0].y = tmp[r][0].y + tmp[r][1].y + tmp[r][2].y;
        y[r][1].x = tmp[r][1].x - tmp[r][2].x - tmp[r][3].x;
        y[r][1].y = tmp[r][1].y - tmp[r][2].y - tmp[r][3].y;
    }
}

// Final output transform: fp32 M -> fp32 out [s][b][co][p]. grid (256, 48=s*16+b)
__global__ void k_otransO(const float* __restrict__ M32,
                          const float* __restrict__ bias,
                          float* __restrict__ Y) {
    int tile = blockIdx.x;
    int zb = blockIdx.y, s = zb >> 4, b = zb & 15;
    int t = threadIdx.x;
    int ty = tile >> 4, tx = tile & 15;

    const float2* M2 = (const float2*)M32;
    size_t jbase = ((size_t)s * 16) * (MPT / 2);
    float2 m[16];
#pragma unroll
    for (int p = 0; p < 16; ++p)
        m[p] = M2[jbase + (size_t)p * (MPT / 2)
                  + ((size_t)b * 256 + tile) * 256 + t];
    float2 y[2][2];
    otrans_math(m, y);
    float2 bv = ((const float2*)bias)[t];
    float* out = Y + (size_t)s * TSZ + (size_t)b * C_ * N_;
    int co0 = 2 * t;
#pragma unroll
    for (int r = 0; r < 2; ++r) {
        int p0 = (2 * ty + r) * HW + 2 * tx;
        out[(size_t)co0 * N_ + p0]           = y[r][0].x + bv.x;
        out[(size_t)co0 * N_ + p0 + 1]       = y[r][1].x + bv.x;
        out[(size_t)(co0 + 1) * N_ + p0]     = y[r][0].y + bv.y;
        out[(size_t)(co0 + 1) * N_ + p0 + 1] = y[r][1].y + bv.y;
    }
}

// ---------------------------------------------------------------------------
// k_gemmRU_all: 3 fused reset+update GEMMs, M=1024 (r|u), 256x128 tiles.
// ---------------------------------------------------------------------------
__global__ void __launch_bounds__(256, 1) k_gemmRU_all(
        const __half* __restrict__ Wru, const __half* __restrict__ aT,
        const __half* __restrict__ exT, const __half* __restrict__ qT,
        const __half* __restrict__ q1T,
        float* __restrict__ hex, float* __restrict__ hq, float* __restrict__ hq1,
        const float* __restrict__ b_r, const float* __restrict__ b_u,
        __half* __restrict__ rhT, float* __restrict__ u) {
    GEMM_PRE();
    int z = blockIdx.z, j = z >> 4, b = z & 15;
    int co0 = blockIdx.y * 256, p0 = blockIdx.x * 128;
    const __half* hTj = sel3(j, exT, qT, q1T);
    const __half* arow = Wru + (size_t)(co0 + t) * (2 * C_);
    const __half* xrow = aT + (size_t)j * TSZ + (size_t)b * N_ * C_ + (size_t)(p0 + (t & 127)) * C_;
    const __half* hrow = hTj + (size_t)b * N_ * C_ + (size_t)(p0 + (t & 127)) * C_;

    auto issue = [&](int it) {
        int ci0 = it * 16;
        uint32_t da = sAs + (it & 3) * ASTG + t * 48;
        const __half* pa = arow + ci0;
        cpa16(da, pa, 16); cpa16(da + 16, pa + 8, 16);
        if (t < 128) {
            uint32_t db = sBs + (it & 3) * BSTG + t * 48;
            const __half* pb = (ci0 < C_) ? (xrow + ci0) : (hrow + ci0 - C_);
            cpa16(db, pb, 16); cpa16(db + 16, pb + 8, 16);
        }
    };

    ZERO_ACC(acc);
    GEMM_PIPE((2 * C_) / 16, issue, acc);

    bool isR = co0 < C_;
    if (isR) {
        const float* hb = sel3cf(j, hex, hq, hq1) + (size_t)b * C_ * N_;
        __half* rh = rhT + (size_t)j * TSZ + (size_t)b * N_ * C_;
#pragma unroll
        for (int mt = 0; mt < 4; ++mt)
#pragma unroll
            for (int nt = 0; nt < 8; ++nt) {
                int row = co0 + wm + mt * 16 + g;
                int col = p0 + wn + nt * 8 + tg * 2;
                float bv0 = b_r[row], bv1 = b_r[row + 8];
                float o0 = sigm(acc[mt][nt][0] + bv0) * hb[(size_t)row * N_ + col];
                float o1 = sigm(acc[mt][nt][1] + bv0) * hb[(size_t)row * N_ + col + 1];
                float o2 = sigm(acc[mt][nt][2] + bv1) * hb[(size_t)(row + 8) * N_ + col];
                float o3 = sigm(acc[mt][nt][3] + bv1) * hb[(size_t)(row + 8) * N_ + col + 1];
                rh[(size_t)col * C_ + row]           = __float2half_rn(o0);
                rh[(size_t)(col + 1) * C_ + row]     = __float2half_rn(o1);
                rh[(size_t)col * C_ + row + 8]       = __float2half_rn(o2);
                rh[(size_t)(col + 1) * C_ + row + 8] = __float2half_rn(o3);
            }
    } else {
        int rbase = co0 - C_;
        float* ub = u + (size_t)j * TSZ + (size_t)b * C_ * N_;
#pragma unroll
        for (int mt = 0; mt < 4; ++mt)
#pragma unroll
            for (int nt = 0; nt < 8; ++nt) {
                int row = rbase + wm + mt * 16 + g;
                int col = p0 + wn + nt * 8 + tg * 2;
                float bv0 = b_u[row], bv1 = b_u[row + 8];
                *(float2*)(ub + (size_t)row * N_ + col) =
                    make_float2(sigm(acc[mt][nt][0] + bv0), sigm(acc[mt][nt][1] + bv0));
                *(float2*)(ub + (size_t)(row + 8) * N_ + col) =
                    make_float2(sigm(acc[mt][nt][2] + bv1), sigm(acc[mt][nt][3] + bv1));
            }
    }
}

// ---------------------------------------------------------------------------
// k_gemmCAND_all: 3 candidate GEMMs, c = tanh(Wc@[x;r*h]+b), 256x128 tiles.
// ---------------------------------------------------------------------------
__global__ void __launch_bounds__(256, 1) k_gemmCAND_all(
        const __half* __restrict__ Wc, const __half* __restrict__ aT,
        const __half* __restrict__ rhT, const float* __restrict__ bias,
        float* __restrict__ cbuf) {
    GEMM_PRE();
    int z = blockIdx.z, j = z >> 4, b = z & 15;
    int co0 = blockIdx.y * 256, p0 = blockIdx.x * 128;
    const __half* arow  = Wc + (size_t)(co0 + t) * (2 * C_);
    const __half* xrow  = aT  + (size_t)j * TSZ + (size_t)b * N_ * C_ + (size_t)(p0 + (t & 127)) * C_;
    const __half* rhrow = rhT + (size_t)j * TSZ + (size_t)b * N_ * C_ + (size_t)(p0 + (t & 127)) * C_;
    float* Yb = cbuf + (size_t)j * TSZ + (size_t)b * C_ * N_;

    auto issue = [&](int it) {
        int ci0 = it * 16;
        uint32_t da = sAs + (it & 3) * ASTG + t * 48;
        const __half* pa = arow + ci0;
        cpa16(da, pa, 16); cpa16(da + 16, pa + 8, 16);
        if (t < 128) {
            uint32_t db = sBs + (it & 3) * BSTG + t * 48;
            const __half* pb = (ci0 < C_) ? (xrow + ci0) : (rhrow + ci0 - C_);
            cpa16(db, pb, 16); cpa16(db + 16, pb + 8, 16);
        }
    };

    ZERO_ACC(acc);
    GEMM_PIPE((2 * C_) / 16, issue, acc);

#pragma unroll
    for (int mt = 0; mt < 4; ++mt)
#pragma unroll
        for (int nt = 0; nt < 8; ++nt) {
            int row = co0 + wm + mt * 16 + g;
            int col = p0 + wn + nt * 8 + tg * 2;
            float bv0 = bias[row], bv1 = bias[row + 8];
            *(float2*)(Yb + (size_t)row * N_ + col) =
                make_float2(tanhf(acc[mt][nt][0] + bv0), tanhf(acc[mt][nt][1] + bv0));
            *(float2*)(Yb + (size_t)(row + 8) * N_ + col) =
                make_float2(tanhf(acc[mt][nt][2] + bv1), tanhf(acc[mt][nt][3] + bv1));
        }
}

// ---------------------------------------------------------------------------
// k_gruout_all: h = h(1-u)+cu for 3 states, emits fp16 mirrors. grid (32,16,48)
// ---------------------------------------------------------------------------
__global__ void k_gruout_all(
        float* __restrict__ hex, float* __restrict__ hq, float* __restrict__ hq1,
        const float* __restrict__ u, const float* __restrict__ c,
        __half* __restrict__ n16_0, __half* __restrict__ n16_1, __half* __restrict__ n16_2,
        __half* __restrict__ nT_0, __half* __restrict__ nT_1, __half* __restrict__ nT_2) {
    __shared__ float tile[32][33];
    int z = blockIdx.z, s = z >> 4, b = z & 15;
    float*       hb = sel3f(s, hex, hq, hq1) + (size_t)b * C_ * N_;
    const float* ub = u + (size_t)s * TSZ + (size_t)b * C_ * N_;
    const float* cb = c + (size_t)s * TSZ + (size_t)b * C_ * N_;
    __half* on = sel3h(s, n16_0, n16_1, n16_2) + (size_t)b * C_ * N_;
    __half* ot = sel3h(s, nT_0, nT_1, nT_2)    + (size_t)b * N_ * C_;
    int n0 = blockIdx.x * 32, c0 = blockIdx.y * 32;
    int tx = threadIdx.x, ty = threadIdx.y;
#pragma unroll
    for (int j = 0; j < 4; ++j) {
        size_t idx = (size_t)(c0 + ty + 8 * j) * N_ + n0 + tx;
        float hv = hb[idx] * (1.f - ub[idx]) + cb[idx] * ub[idx];
        hb[idx] = hv;
        on[idx] = __float2half_rn(hv);
        tile[ty + 8 * j][tx] = hv;
    }
    __syncthreads();
#pragma unroll
    for (int j = 0; j < 4; ++j)
        ot[(size_t)(n0 + ty + 8 * j) * C_ + c0 + tx] = __float2half_rn(tile[tx][ty + 8 * j]);
}

// ---------------------------------------------------------------------------
// Prep kernels
// ---------------------------------------------------------------------------
__global__ void k_prep_g(const float* __restrict__ wr, const float* __restrict__ wu,
                         const float* __restrict__ wc,
                         __half* __restrict__ oru, __half* __restrict__ oc) {
    size_t i = (size_t)blockIdx.x * 256 + threadIdx.x;
    size_t half = (size_t)C_ * 2 * C_;
    if (i < half) oru[i] = __float2half_rn(wr[i]);
    else if (i < 2 * half) oru[i] = __float2half_rn(wu[i - half]);
    else if (i < 3 * half) oc[i - 2 * half] = __float2half_rn(wc[i - 2 * half]);
}

__global__ void k_premirror(
        const float* __restrict__ in1, const float* __restrict__ in2,
        const float* __restrict__ in3,
        float* __restrict__ hex, float* __restrict__ hq, float* __restrict__ hq1,
        __half* __restrict__ m16_0, __half* __restrict__ m16_1, __half* __restrict__ m16_2,
        __half* __restrict__ mT_0, __half* __restrict__ mT_1, __half* __restrict__ mT_2,
        __half* __restrict__ i1T, __half* __restrict__ i2T, __half* __restrict__ i3T) {
    __shared__ float tile[32][33];
    int z = blockIdx.z;
    int tx = threadIdx.x, ty = threadIdx.y;
    int n0 = blockIdx.x * 32, c0 = blockIdx.y * 32;
    if (z < 48) {
        int s = z >> 4, b = z & 15;
        const float* ib = sel3cf(s, in1, in2, in3) + (size_t)b * C_ * N_;
        float* hb = sel3f(s, hex, hq, hq1) + (size_t)b * C_ * N_;
        __half* on = sel3h(s, m16_0, m16_1, m16_2) + (size_t)b * C_ * N_;
        __half* ot = sel3h(s, mT_0, mT_1, mT_2)    + (size_t)b * N_ * C_;
#pragma unroll
        for (int j = 0; j < 4; ++j) {
            size_t idx = (size_t)(c0 + ty + 8 * j) * N_ + n0 + tx;
            float v = ib[idx];
            hb[idx] = v;
            on[idx] = __float2half_rn(v);
            tile[ty + 8 * j][tx] = v;
        }
        __syncthreads();
#pragma unroll
        for (int j = 0; j < 4; ++j)
            ot[(size_t)(n0 + ty + 8 * j) * C_ + c0 + tx] = __float2half_rn(tile[tx][ty + 8 * j]);
    } else {
        int s = (z - 48) >> 4, b = (z - 48) & 15;
        const float* ib = sel3cf(s, in1, in2, in3) + (size_t)b * C_ * N_;
        __half* ot = sel3h(s, i1T, i2T, i3T) + (size_t)b * N_ * C_;
#pragma unroll
        for (int j = 0; j < 4; ++j)
            tile[ty + 8 * j][tx] = ib[(size_t)(c0 + ty + 8 * j) * N_ + n0 + tx];
        __syncthreads();
#pragma unroll
        for (int j = 0; j < 4; ++j)
            ot[(size_t)(n0 + ty + 8 * j) * C_ + c0 + tx] = __float2half_rn(tile[tx][ty + 8 * j]);
    }
}

// ---------------------------------------------------------------------------
// Host orchestration
// ---------------------------------------------------------------------------
extern "C" void kernel_launch(void* const* d_in, const int* in_sizes, int n_in,
                              void* d_out, int out_size) {
    const float* in1      = (const float*)d_in[0];
    const float* in2      = (const float*)d_in[1];
    const float* in3      = (const float*)d_in[2];
    const float* w_fusion = (const float*)d_in[3];
    const float* b_fusion = (const float*)d_in[4];
    const float* w_out    = (const float*)d_in[5];
    const float* b_out    = (const float*)d_in[6];
    const float* w_reset  = (const float*)d_in[7];
    const float* b_reset  = (const float*)d_in[8];
    const float* w_update = (const float*)d_in[9];
    const float* b_update = (const float*)d_in[10];
    const float* w_cand   = (const float*)d_in[11];
    const float* b_cand   = (const float*)d_in[12];
    float* out = (float*)d_out;

    cudaFuncSetAttribute(k_scores_all,   cudaFuncAttributeMaxDynamicSharedMemorySize, SMEM_DYN);
    cudaFuncSetAttribute(k_attmmT_all,   cudaFuncAttributeMaxDynamicSharedMemorySize, SMEM_DYN);
    cudaFuncSetAttribute(k_wino,         cudaFuncAttributeMaxDynamicSharedMemorySize, SMEM_DYN);
    cudaFuncSetAttribute(k_winoF4,       cudaFuncAttributeMaxDynamicSharedMemorySize, SMEM_DYN);
    cudaFuncSetAttribute(k_gemmRU_all,   cudaFuncAttributeMaxDynamicSharedMemorySize, SMEM_DYN);
    cudaFuncSetAttribute(k_gemmCAND_all, cudaFuncAttributeMaxDynamicSharedMemorySize, SMEM_DYN);

    float *S, *ex, *q, *q1, *u, *c, *M32;
    __half *M164, *V4, *U4, *P16, *OT, *aT, *rhT, *in1T, *in2T, *in3T, *V, *Uo;
    __half *wru16, *wc16;
    __half *m16a[3], *m16b[3], *mTa[3], *mTb[3];
    cudaGetSymbolAddress((void**)&S,    g_S);
    cudaGetSymbolAddress((void**)&ex,   g_ex);
    cudaGetSymbolAddress((void**)&q,    g_q);
    cudaGetSymbolAddress((void**)&q1,   g_q1);
    cudaGetSymbolAddress((void**)&u,    g_u);
    cudaGetSymbolAddress((void**)&c,    g_c);
    cudaGetSymbolAddress((void**)&M32,  g_M32);
    cudaGetSymbolAddress((void**)&M164, g_M164);
    cudaGetSymbolAddress((void**)&V4,   g_V4);
    cudaGetSymbolAddress((void**)&U4,   g_U4);
    cudaGetSymbolAddress((void**)&P16,  g_P16);
    cudaGetSymbolAddress((void**)&OT,   g_OT);
    cudaGetSymbolAddress((void**)&aT,   g_aT);
    cudaGetSymbolAddress((void**)&rhT,  g_rhT);
    cudaGetSymbolAddress((void**)&V,    g_V);
    cudaGetSymbolAddress((void**)&Uo,   g_Uo);
    cudaGetSymbolAddress((void**)&in1T, g_in1T16);
    cudaGetSymbolAddress((void**)&in2T, g_in2T16);
    cudaGetSymbolAddress((void**)&in3T, g_in3T16);
    cudaGetSymbolAddress((void**)&wru16, g_wru16);
    cudaGetSymbolAddress((void**)&wc16, g_wc16);
    cudaGetSymbolAddress((void**)&m16a[0], g_ex16a);
    cudaGetSymbolAddress((void**)&m16a[1], g_q16a);
    cudaGetSymbolAddress((void**)&m16a[2], g_q116a);
    cudaGetSymbolAddress((void**)&m16b[0], g_ex16b);
    cudaGetSymbolAddress((void**)&m16b[1], g_q16b);
    cudaGetSymbolAddress((void**)&m16b[2], g_q116b);
    cudaGetSymbolAddress((void**)&mTa[0], g_exT16a);
    cudaGetSymbolAddress((void**)&mTa[1], g_qT16a);
    cudaGetSymbolAddress((void**)&mTa[2], g_q1T16a);
    cudaGetSymbolAddress((void**)&mTb[0], g_exT16b);
    cudaGetSymbolAddress((void**)&mTb[1], g_qT16b);
    cudaGetSymbolAddress((void**)&mTb[2], g_q1T16b);

    const int GG = (int)((3 * (size_t)C_ * 2 * C_ + 255) / 256);

    // prep (4 launches)
    k_prep_g<<<GG, 256>>>(w_reset, w_update, w_cand, wru16, wc16);
    k_wt_wino4<<<2048, 256>>>(w_fusion, U4);
    k_wt_wino<<<2048, 256>>>(w_out, Uo);
    k_premirror<<<dim3(32, 16, 96), dim3(32, 8)>>>(
        in1, in2, in3, ex, q, q1,
        m16a[0], m16a[1], m16a[2], mTa[0], mTa[1], mTa[2],
        in1T, in2T, in3T);

    __half** cur16 = m16a;  __half** curT = mTa;
    __half** nw16  = m16b;  __half** nwT  = mTb;

    for (int round = 0; round < 5; ++round) {
        k_scores_all<<<dim3(8, 4, 96), 256, SMEM_DYN>>>(curT[0], curT[1], curT[2], S);
        k_softmax_all<<<6 * B_ * N_, 256>>>(S, P16);
        k_attmmT_all<<<dim3(4, 4, 96), 256, SMEM_DYN>>>(P16, cur16[0], cur16[1], cur16[2], OT);

        // fusion convs via Winograd F(4x4,3x3), fp16 M
        k_dtransF4<<<dim3(64, 48), 256>>>(OT, V4);
        k_winoF4<<<dim3(4, 4, 108), 256, SMEM_DYN>>>(V4, U4, M164);
        k_otransF4<<<dim3(64, 48), 256>>>(M164, b_fusion, aT);

        k_gemmRU_all<<<dim3(8, 4, 48), 256, SMEM_DYN>>>(
            wru16, aT, curT[0], curT[1], curT[2], ex, q, q1,
            b_reset, b_update, rhT, u);
        k_gemmCAND_all<<<dim3(8, 2, 48), 256, SMEM_DYN>>>(wc16, aT, rhT, b_cand, c);
        k_gruout_all<<<dim3(32, 16, 48), dim3(32, 8)>>>(
            ex, q, q1, u, c,
            nw16[0], nw16[1], nw16[2], nwT[0], nwT[1], nwT[2]);

        __half** t16 = cur16; cur16 = nw16; nw16 = t16;
        __half** tT  = curT;  curT  = nwT;  nwT  = tT;
    }

    // final output convs via Winograd F(2,3) (fp32 M — output-precision path)
    k_dtransO<<<dim3(256, 48), 256>>>(curT[0], curT[1], curT[2],
                                      in1T, in2T, in3T, V);
    k_wino<<<dim3(4, 1, 768), 256, SMEM_DYN>>>(V, Uo, M32);
    k_otransO<<<dim3(256, 48), 256>>>(M32, b_out, out);
}